// round 14
// baseline (speedup 1.0000x reference)
#include <cuda_runtime.h>
#include <cuda_bf16.h>
#include <cuda_fp16.h>
#include <cstdint>
#include <cstddef>

#define TOTAL   8192
#define DIM     1280
#define HEADS   16
#define HD      80
#define NCHUNKS 8
#define CHUNK   1024
#define K_DIM   1280
#define N_QKV   3840

// ---------------- scratch (device globals) ----------------------------------
__device__ float g_q [TOTAL * DIM];
__device__ float g_k [TOTAL * DIM];

__device__ __half g_hs_h[TOTAL * K_DIM];
__device__ __half g_hs_l[TOTAL * K_DIM];
__device__ __half g_wq_h[N_QKV * K_DIM];
__device__ __half g_wp_h[DIM * K_DIM];
__device__ __half g_ao_h[TOTAL * DIM];
__device__ __half g_ao_l[TOTAL * DIM];

__device__ __half g_qh[TOTAL * DIM];
__device__ __half g_ql[TOTAL * DIM];
__device__ __half g_kh[TOTAL * DIM];
__device__ __half g_vh[TOTAL * DIM];

// ---------------- PTX helpers ------------------------------------------------
__device__ __forceinline__ uint32_t smem_u32(const void* p) {
    uint32_t r;
    asm("{ .reg .u64 t; cvta.to.shared.u64 t, %1; cvt.u32.u64 %0, t; }"
        : "=r"(r) : "l"(p));
    return r;
}
__device__ __forceinline__ void cp16(uint32_t dst, const void* src) {
    asm volatile("cp.async.cg.shared.global [%0], [%1], 16;" :: "r"(dst), "l"(src));
}
__device__ __forceinline__ void ldmx4(uint32_t* a, uint32_t addr) {
    asm volatile("ldmatrix.sync.aligned.m8n8.x4.shared.b16 {%0,%1,%2,%3}, [%4];"
                 : "=r"(a[0]), "=r"(a[1]), "=r"(a[2]), "=r"(a[3]) : "r"(addr));
}
__device__ __forceinline__ void ldmx4t(uint32_t* a, uint32_t addr) {
    asm volatile("ldmatrix.sync.aligned.m8n8.x4.trans.shared.b16 {%0,%1,%2,%3}, [%4];"
                 : "=r"(a[0]), "=r"(a[1]), "=r"(a[2]), "=r"(a[3]) : "r"(addr));
}
__device__ __forceinline__ void ldmB(uint32_t* b, uint32_t addr) {
    asm volatile("ldmatrix.sync.aligned.m8n8.x2.shared.b16 {%0,%1}, [%2];"
                 : "=r"(b[0]), "=r"(b[1]) : "r"(addr));
}
// fp16 mma
__device__ __forceinline__ void mma16816h(float* d, const uint32_t* a, const uint32_t* b) {
    asm volatile(
        "mma.sync.aligned.m16n8k16.row.col.f32.f16.f16.f32 "
        "{%0,%1,%2,%3}, {%4,%5,%6,%7}, {%8,%9}, {%0,%1,%2,%3};"
        : "+f"(d[0]), "+f"(d[1]), "+f"(d[2]), "+f"(d[3])
        : "r"(a[0]), "r"(a[1]), "r"(a[2]), "r"(a[3]), "r"(b[0]), "r"(b[1]));
}
__device__ __forceinline__ float ex2(float x) {
    float r;
    asm("ex2.approx.f32 %0, %1;" : "=f"(r) : "f"(x));
    return r;
}
__device__ __forceinline__ void split2h(float a, float b, uint32_t& hi, uint32_t& lo) {
    __half2 h = __floats2half2_rn(a, b);
    float ra = a - __low2float(h);
    float rb = b - __high2float(h);
    __half2 l = __floats2half2_rn(ra, rb);
    hi = *(uint32_t*)&h;
    lo = *(uint32_t*)&l;
}
// mbarrier ops
__device__ __forceinline__ void mbar_init(uint32_t addr, uint32_t cnt) {
    asm volatile("mbarrier.init.shared.b64 [%0], %1;" :: "r"(addr), "r"(cnt) : "memory");
}
__device__ __forceinline__ void mbar_arrive(uint32_t addr) {
    asm volatile("mbarrier.arrive.shared.b64 _, [%0];" :: "r"(addr) : "memory");
}
__device__ __forceinline__ void cpasync_mbar_arrive(uint32_t addr) {
    asm volatile("cp.async.mbarrier.arrive.noinc.shared.b64 [%0];" :: "r"(addr) : "memory");
}
__device__ __forceinline__ void mbar_wait(uint32_t addr, uint32_t parity) {
    asm volatile(
        "{\n\t"
        ".reg .pred P1;\n\t"
        "WL%=:\n\t"
        "mbarrier.try_wait.parity.acquire.cta.shared::cta.b64 P1, [%0], %1, 0x989680;\n\t"
        "@P1 bra WD%=;\n\t"
        "bra WL%=;\n\t"
        "WD%=:\n\t"
        "}"
        :: "r"(addr), "r"(parity) : "memory");
}

// ---------------------------------------------------------------------------
// fp32 -> fp16 hi/lo split (activations)
// ---------------------------------------------------------------------------
__global__ void cvt_h2(const float* __restrict__ x,
                       __half* __restrict__ hi, __half* __restrict__ lo, int n4)
{
    int i = blockIdx.x * blockDim.x + threadIdx.x;
    if (i >= n4) return;
    float4 f = ((const float4*)x)[i];
    uint32_t h0, l0, h1, l1;
    split2h(f.x, f.y, h0, l0);
    split2h(f.z, f.w, h1, l1);
    ((uint32_t*)hi)[i * 2 + 0] = h0; ((uint32_t*)hi)[i * 2 + 1] = h1;
    ((uint32_t*)lo)[i * 2 + 0] = l0; ((uint32_t*)lo)[i * 2 + 1] = l1;
}

// fp32 -> fp16 (weights; single rounding)
__global__ void cvt_h1(const float* __restrict__ x, __half* __restrict__ h, int n4)
{
    int i = blockIdx.x * blockDim.x + threadIdx.x;
    if (i >= n4) return;
    float4 f = ((const float4*)x)[i];
    __half2 p0 = __floats2half2_rn(f.x, f.y);
    __half2 p1 = __floats2half2_rn(f.z, f.w);
    ((uint32_t*)h)[i * 2 + 0] = *(uint32_t*)&p0;
    ((uint32_t*)h)[i * 2 + 1] = *(uint32_t*)&p1;
}

// ---------------------------------------------------------------------------
// Warp-specialized fp16 GEMM, 2-pass: C = Ah*Bh + Al*Bh  (+ bias)
// 16 consumer warps (32x32 tile each) + 2 producer warps, 5-stage pipeline.
// EPI==0: parts 0/1 (Q,K) -> fp32 O0/O1; part 2 (V) -> fp16 Ovh.
// EPI==1: fp32 store to O0.
// ---------------------------------------------------------------------------
#define KC       32
#define NCH      40
#define STRIDE   40
#define TILE_B   (128 * STRIDE * 2)    // 10240
#define STAGE_B  (3 * TILE_B)          // 30720 (Ah, Al, Bh)
#define NSTG     5
#define GSMEM    (NSTG * STAGE_B)      // 153600
#define NCONS    512                   // 16 consumer warps
#define NPROD    64                    // 2 producer warps
#define NTHR     (NCONS + NPROD)

template <int EPI>
__global__ __launch_bounds__(NTHR, 1)
void mma_gemm(const __half* __restrict__ Ah, const __half* __restrict__ Al,
              const __half* __restrict__ Bh,
              const float* __restrict__ bias,
              float* __restrict__ O0, float* __restrict__ O1,
              __half* __restrict__ Ovh)
{
    extern __shared__ __half smem[];
    __shared__ __align__(8) uint64_t bar_full [NSTG];
    __shared__ __align__(8) uint64_t bar_empty[NSTG];

    const uint32_t sbase = smem_u32(smem);
    const int tid  = threadIdx.x;
    const int m0   = blockIdx.y * 128;
    const int n0   = blockIdx.x * 128;

    uint32_t full[NSTG], empty[NSTG];
#pragma unroll
    for (int s = 0; s < NSTG; s++) {
        full[s]  = smem_u32(&bar_full[s]);
        empty[s] = smem_u32(&bar_empty[s]);
    }
    if (tid == 0) {
#pragma unroll
        for (int s = 0; s < NSTG; s++) {
            mbar_init(full[s],  NPROD);
            mbar_init(empty[s], NCONS);
        }
    }
    __syncthreads();

    if (tid >= NCONS) {
        // ---------------- producer warps --------------------------------------
        const int ptid = tid - NCONS;    // 0..63
        const __half* srcs[3] = {
            Ah + (size_t)m0 * K_DIM, Al + (size_t)m0 * K_DIM,
            Bh + (size_t)n0 * K_DIM };
        int stage = 0, phase = 1;
        for (int ch = 0; ch < NCH; ch++) {
            mbar_wait(empty[stage], phase);
            const int k0 = ch * KC;
            const uint32_t sb = sbase + stage * STAGE_B;
#pragma unroll
            for (int t = 0; t < 24; t++) {
                int idx  = ptid + t * 64;   // 0..1535
                int tile = idx >> 9;        // 0..2
                int rem  = idx & 511;
                int row  = rem >> 2;
                int seg  = rem & 3;
                cp16(sb + tile * TILE_B + row * (STRIDE * 2) + seg * 16,
                     srcs[tile] + (size_t)row * K_DIM + k0 + seg * 8);
            }
            cpasync_mbar_arrive(full[stage]);
            if (++stage == NSTG) { stage = 0; phase ^= 1; }
        }
        return;
    }

    // ---------------- consumer warps (16 x 32x32) ------------------------------
    const int wid  = tid >> 5;           // 0..15
    const int lane = tid & 31;
    const int wm   = (wid >> 2) * 32;    // 0,32,64,96
    const int wn   = (wid & 3) * 32;     // 0,32,64,96

    float acc[2][4][4];
#pragma unroll
    for (int i = 0; i < 2; i++)
#pragma unroll
        for (int j = 0; j < 4; j++)
#pragma unroll
            for (int r = 0; r < 4; r++) acc[i][j][r] = 0.f;

    const int arow  = lane & 15;
    const int acol8 = (lane >> 4) * 8;
    const int brow  = lane & 7;
    const int bcolo = ((lane >> 3) & 1) * 8;

    int stage = 0, phase = 0;
    for (int ch = 0; ch < NCH; ch++) {
        mbar_wait(full[stage], phase);

        const uint32_t sb  = sbase + stage * STAGE_B;
        const uint32_t sAh = sb;
        const uint32_t sAl = sb + TILE_B;
        const uint32_t sBh = sb + 2 * TILE_B;

#pragma unroll
        for (int kk = 0; kk < 2; kk++) {
            uint32_t aH[8], aL[8];
#pragma unroll
            for (int mt = 0; mt < 2; mt++) {
                uint32_t off = ((wm + mt * 16 + arow) * STRIDE + kk * 16 + acol8) * 2;
                ldmx4(aH + mt * 4, sAh + off);
                ldmx4(aL + mt * 4, sAl + off);
            }
#pragma unroll
            for (int nt = 0; nt < 4; nt++) {
                uint32_t bh[2];
                uint32_t off = ((wn + nt * 8 + brow) * STRIDE + kk * 16 + bcolo) * 2;
                ldmB(bh, sBh + off);
#pragma unroll
                for (int mt = 0; mt < 2; mt++) {
                    mma16816h(acc[mt][nt], aH + mt * 4, bh);
                    mma16816h(acc[mt][nt], aL + mt * 4, bh);
                }
            }
        }
        mbar_arrive(empty[stage]);
        if (++stage == NSTG) { stage = 0; phase ^= 1; }
    }

    // ---- epilogue ----
    if (EPI == 0 && n0 >= 2 * DIM) {
        // V part: single fp16 (no RoPE, consumed as B operand of PV GEMM)
        const int ccol0 = n0 - 2 * DIM;
#pragma unroll
        for (int mt = 0; mt < 2; mt++) {
#pragma unroll
            for (int nt = 0; nt < 4; nt++) {
                int row   = m0 + wm + mt * 16 + (lane >> 2);
                int bcolg = n0 + wn + nt * 8 + (lane & 3) * 2;
                int col   = ccol0 + wn + nt * 8 + (lane & 3) * 2;
                float2 bb = *(const float2*)&bias[bcolg];
                __half2 v0 = __floats2half2_rn(acc[mt][nt][0] + bb.x,
                                               acc[mt][nt][1] + bb.y);
                __half2 v1 = __floats2half2_rn(acc[mt][nt][2] + bb.x,
                                               acc[mt][nt][3] + bb.y);
                *(uint32_t*)&Ovh[(size_t)row * DIM + col]       = *(uint32_t*)&v0;
                *(uint32_t*)&Ovh[(size_t)(row + 8) * DIM + col] = *(uint32_t*)&v1;
            }
        }
    } else {
        float* dst;
        int ccol0;
        if (EPI == 0) {
            int part = n0 / DIM;
            dst   = (part == 0) ? O0 : O1;
            ccol0 = n0 - part * DIM;
        } else {
            dst   = O0;
            ccol0 = n0;
        }
#pragma unroll
        for (int mt = 0; mt < 2; mt++) {
#pragma unroll
            for (int nt = 0; nt < 4; nt++) {
                int row   = m0 + wm + mt * 16 + (lane >> 2);
                int bcolg = n0 + wn + nt * 8 + (lane & 3) * 2;
                int col   = ccol0 + wn + nt * 8 + (lane & 3) * 2;
                float2 bb = *(const float2*)&bias[bcolg];
                float2 v0, v1;
                v0.x = acc[mt][nt][0] + bb.x;  v0.y = acc[mt][nt][1] + bb.y;
                v1.x = acc[mt][nt][2] + bb.x;  v1.y = acc[mt][nt][3] + bb.y;
                *(float2*)&dst[(size_t)row * DIM + col]       = v0;
                *(float2*)&dst[(size_t)(row + 8) * DIM + col] = v1;
            }
        }
    }
}

// ---------------------------------------------------------------------------
// RoPE + scale: q -> fp16 hi/lo (scaled), k -> fp16 single
// ---------------------------------------------------------------------------
__global__ __launch_bounds__(640)
void rope_cvt(const float* __restrict__ gq, const float* __restrict__ gk,
              const float* __restrict__ cosb, const float* __restrict__ sinb,
              __half* __restrict__ qh, __half* __restrict__ ql,
              __half* __restrict__ kh)
{
    const float QSC = 0.11180339887498949f * 1.4426950408889634f;
    const int t = blockIdx.x;
    const int p = threadIdx.x;

    int h = p / 40, d = p - (p / 40) * 40;
    size_t base = (size_t)t * DIM + h * HD;
    float c0 = cosb[t * HD + d],      s0 = sinb[t * HD + d];
    float c1 = cosb[t * HD + d + 40], s1 = sinb[t * HD + d + 40];

    float a = gq[base + d], b = gq[base + d + 40];
    float q0 = (a * c0 - b * s0) * QSC;
    float q1 = (b * c1 + a * s1) * QSC;
    __half h0 = __float2half_rn(q0);
    __half h1 = __float2half_rn(q1);
    qh[base + d]      = h0;
    qh[base + d + 40] = h1;
    ql[base + d]      = __float2half_rn(q0 - __half2float(h0));
    ql[base + d + 40] = __float2half_rn(q1 - __half2float(h1));

    a = gk[base + d]; b = gk[base + d + 40];
    kh[base + d]      = __float2half_rn(a * c0 - b * s0);
    kh[base + d + 40] = __float2half_rn(b * c1 + a * s1);
}

// ---------------------------------------------------------------------------
// Flash attention on fp16 mma.sync, 2-pass (Qh/Ql vs K; Ph/Pl vs V):
// 8 consumer warps + 2 producer warps, 5-stage KV mbarrier ring. (R13 exact)
// ---------------------------------------------------------------------------
#define AST      88
#define ATB      (64 * AST)            // elems per buf (5632)
#define ASTAGE   (2 * ATB)             // K + V per stage (11264)
#define ANSTG    5
#define ASMEM    (ANSTG * ASTAGE * 2)  // 112640 B
#define ANCONS   256
#define ANPROD   64
#define ANTHR    (ANCONS + ANPROD)

__global__ __launch_bounds__(ANTHR, 1)
void attn_mma(const __half* __restrict__ qh, const __half* __restrict__ ql,
              const __half* __restrict__ kh, const __half* __restrict__ vh,
              __half* __restrict__ aoh, __half* __restrict__ aol)
{
    extern __shared__ __half asmem[];
    __shared__ __align__(8) uint64_t abar_full [ANSTG];
    __shared__ __align__(8) uint64_t abar_empty[ANSTG];

    const uint32_t sbase = smem_u32(asmem);
    const int tid   = threadIdx.x;
    const int chunk = blockIdx.z;
    const int head  = blockIdx.y;
    const int q0    = blockIdx.x * 128;

    uint32_t full[ANSTG], empty[ANSTG];
#pragma unroll
    for (int s = 0; s < ANSTG; s++) {
        full[s]  = smem_u32(&abar_full[s]);
        empty[s] = smem_u32(&abar_empty[s]);
    }
    if (tid == 0) {
#pragma unroll
        for (int s = 0; s < ANSTG; s++) {
            mbar_init(full[s],  ANPROD);
            mbar_init(empty[s], ANCONS);
        }
    }

    // ---- stage Q (hi/lo) through smem -----------------------------------------
    if (tid < ANCONS) {
        const __half* srcq[2] = { qh, ql };
#pragma unroll
        for (int t = 0; t < 10; t++) {
            int idx = tid + t * 256;
            int buf = idx / 1280;
            int rem = idx - buf * 1280;
            int row = rem / 10;
            int seg = rem - row * 10;
            cp16(sbase + (buf * (128 * AST) + row * AST + seg * 8) * 2,
                 srcq[buf] + (size_t)(chunk * CHUNK + q0 + row) * DIM + head * HD + seg * 8);
        }
        asm volatile("cp.async.commit_group;");
        asm volatile("cp.async.wait_group 0;");
    }
    __syncthreads();

    if (tid >= ANCONS) {
        // ---------------- producer warps ----------------------------------------
        const int ptid = tid - ANCONS;
        __syncthreads();                 // consumers finish reading Q from smem
        const __half* srckv[2] = { kh, vh };
        int st = 0, ph = 1;
        for (int t = 0; t < 16; t++) {
            mbar_wait(empty[st], ph);
            const int krow0 = chunk * CHUNK + t * 64;
            const uint32_t sb = sbase + (st * ASTAGE) * 2;
#pragma unroll
            for (int it = 0; it < 20; it++) {
                int idx = ptid + it * 64;      // 0..1279
                int buf = idx / 640;
                int rem = idx - buf * 640;
                int row = rem / 10;
                int seg = rem - row * 10;
                cp16(sb + (buf * ATB + row * AST + seg * 8) * 2,
                     srckv[buf] + (size_t)(krow0 + row) * DIM + head * HD + seg * 8);
            }
            cpasync_mbar_arrive(full[st]);
            if (++st == ANSTG) { st = 0; ph ^= 1; }
        }
        return;
    }

    // ---------------- consumer warps --------------------------------------------
    const int wid  = tid >> 5;
    const int lane = tid & 31;
    const int wm   = wid * 16;

    uint32_t aQh[5][4], aQl[5][4];
    {
        const int arow = lane & 15;
        const int acol8 = 8 * (lane >> 4);
#pragma unroll
        for (int ks = 0; ks < 5; ks++) {
            uint32_t off = ((wm + arow) * AST + ks * 16 + acol8) * 2;
            ldmx4(aQh[ks], sbase + off);
            ldmx4(aQl[ks], sbase + (128 * AST) * 2 + off);
        }
    }
    __syncthreads();   // release smem to producers

    float o[10][4];
#pragma unroll
    for (int i = 0; i < 10; i++)
#pragma unroll
        for (int r = 0; r < 4; r++) o[i][r] = 0.f;
    float mrow0 = -1e30f, mrow1 = -1e30f, lrow0 = 0.f, lrow1 = 0.f;

    int st = 0, ph = 0;
    for (int t = 0; t < 16; t++) {
        mbar_wait(full[st], ph);

        const uint32_t sb = sbase + (st * ASTAGE) * 2;
        const uint32_t sK = sb;
        const uint32_t sV = sb + ATB * 2;

        // ---- S = Q K^T (2 passes) -----------------------------------------------
        float S[8][4];
#pragma unroll
        for (int f = 0; f < 8; f++)
#pragma unroll
            for (int r = 0; r < 4; r++) S[f][r] = 0.f;

#pragma unroll
        for (int ks = 0; ks < 5; ks++) {
#pragma unroll
            for (int ng = 0; ng < 4; ng++) {
                uint32_t bh[4];
                uint32_t off = ((ng * 16 + 8 * (lane >> 4) + (lane & 7)) * AST
                                + ks * 16 + 8 * ((lane >> 3) & 1)) * 2;
                ldmx4(bh, sK + off);
                mma16816h(S[2 * ng],     aQh[ks], bh);
                mma16816h(S[2 * ng],     aQl[ks], bh);
                mma16816h(S[2 * ng + 1], aQh[ks], bh + 2);
                mma16816h(S[2 * ng + 1], aQl[ks], bh + 2);
            }
        }

        // ---- online softmax (base 2) --------------------------------------------
        float mx0 = S[0][0], mx1 = S[0][2];
#pragma unroll
        for (int f = 0; f < 8; f++) {
            mx0 = fmaxf(mx0, fmaxf(S[f][0], S[f][1]));
            mx1 = fmaxf(mx1, fmaxf(S[f][2], S[f][3]));
        }
        mx0 = fmaxf(mx0, __shfl_xor_sync(0xffffffff, mx0, 1));
        mx0 = fmaxf(mx0, __shfl_xor_sync(0xffffffff, mx0, 2));
        mx1 = fmaxf(mx1, __shfl_xor_sync(0xffffffff, mx1, 1));
        mx1 = fmaxf(mx1, __shfl_xor_sync(0xffffffff, mx1, 2));

        float mn0 = fmaxf(mrow0, mx0), mn1 = fmaxf(mrow1, mx1);
        float al0 = ex2(mrow0 - mn0),  al1 = ex2(mrow1 - mn1);
        mrow0 = mn0; mrow1 = mn1;
#pragma unroll
        for (int i = 0; i < 10; i++) {
            o[i][0] *= al0; o[i][1] *= al0;
            o[i][2] *= al1; o[i][3] *= al1;
        }
        float rs0 = 0.f, rs1 = 0.f;
#pragma unroll
        for (int f = 0; f < 8; f++) {
            S[f][0] = ex2(S[f][0] - mn0); rs0 += S[f][0];
            S[f][1] = ex2(S[f][1] - mn0); rs0 += S[f][1];
            S[f][2] = ex2(S[f][2] - mn1); rs1 += S[f][2];
            S[f][3] = ex2(S[f][3] - mn1); rs1 += S[f][3];
        }
        rs0 += __shfl_xor_sync(0xffffffff, rs0, 1);
        rs0 += __shfl_xor_sync(0xffffffff, rs0, 2);
        rs1 += __shfl_xor_sync(0xffffffff, rs1, 1);
        rs1 += __shfl_xor_sync(0xffffffff, rs1, 2);
        lrow0 = lrow0 * al0 + rs0;
        lrow1 = lrow1 * al1 + rs1;

        // ---- P (fp16 hi/lo a-frags) ----------------------------------------------
        uint32_t pH[4][4], pL[4][4];
#pragma unroll
        for (int j = 0; j < 4; j++) {
            split2h(S[2 * j][0],     S[2 * j][1],     pH[j][0], pL[j][0]);
            split2h(S[2 * j][2],     S[2 * j][3],     pH[j][1], pL[j][1]);
            split2h(S[2 * j + 1][0], S[2 * j + 1][1], pH[j][2], pL[j][2]);
            split2h(S[2 * j + 1][2], S[2 * j + 1][3], pH[j][3], pL[j][3]);
        }

        // ---- O += P V (2 passes) ---------------------------------------------------
#pragma unroll
        for (int j = 0; j < 4; j++) {
#pragma unroll
            for (int ng = 0; ng < 5; ng++) {
                uint32_t bv[4];
                uint32_t off = ((j * 16 + (lane & 15)) * AST
                                + ng * 16 + 8 * (lane >> 4)) * 2;
                ldmx4t(bv, sV + off);
                mma16816h(o[2 * ng],     pH[j], bv);
                mma16816h(o[2 * ng],     pL[j], bv);
                mma16816h(o[2 * ng + 1], pH[j], bv + 2);
                mma16816h(o[2 * ng + 1], pL[j], bv + 2);
            }
        }
        mbar_arrive(empty[st]);
        if (++st == ANSTG) { st = 0; ph ^= 1; }
    }

    // ---- normalize + store fp16 hi/lo (for proj GEMM) -------------------------
    float inv0 = 1.f / lrow0, inv1 = 1.f / lrow1;
    const int row0 = chunk * CHUNK + q0 + wm + (lane >> 2);
    const int col0 = head * HD + 2 * (lane & 3);
#pragma unroll
    for (int nt = 0; nt < 10; nt++) {
        uint32_t hi, lo;
        size_t idx0 = (size_t)row0 * DIM + col0 + nt * 8;
        split2h(o[nt][0] * inv0, o[nt][1] * inv0, hi, lo);
        *(uint32_t*)&aoh[idx0] = hi;
        *(uint32_t*)&aol[idx0] = lo;
        size_t idx1 = (size_t)(row0 + 8) * DIM + col0 + nt * 8;
        split2h(o[nt][2] * inv1, o[nt][3] * inv1, hi, lo);
        *(uint32_t*)&aoh[idx1] = hi;
        *(uint32_t*)&aol[idx1] = lo;
    }
}

// ---------------------------------------------------------------------------
// Launch
// ---------------------------------------------------------------------------
extern "C" void kernel_launch(void* const* d_in, const int* in_sizes, int n_in,
                              void* d_out, int out_size)
{
    const float* hs    = (const float*)d_in[0];
    const float* cosb  = (const float*)d_in[1];
    const float* sinb  = (const float*)d_in[2];
    const float* qkvw  = (const float*)d_in[3];
    const float* qkvb  = (const float*)d_in[4];
    const float* projw = (const float*)d_in[5];
    const float* projb = (const float*)d_in[6];
    float* out = (float*)d_out;
    (void)in_sizes; (void)n_in; (void)out_size;

    float *gq, *gk;
    cudaGetSymbolAddress((void**)&gq, g_q);
    cudaGetSymbolAddress((void**)&gk, g_k);

    __half *hsh, *hsl, *wqh, *wph, *aoh, *aol, *qh, *ql, *kh, *vh;
    cudaGetSymbolAddress((void**)&hsh, g_hs_h);
    cudaGetSymbolAddress((void**)&hsl, g_hs_l);
    cudaGetSymbolAddress((void**)&wqh, g_wq_h);
    cudaGetSymbolAddress((void**)&wph, g_wp_h);
    cudaGetSymbolAddress((void**)&aoh, g_ao_h);
    cudaGetSymbolAddress((void**)&aol, g_ao_l);
    cudaGetSymbolAddress((void**)&qh, g_qh);
    cudaGetSymbolAddress((void**)&ql, g_ql);
    cudaGetSymbolAddress((void**)&kh, g_kh);
    cudaGetSymbolAddress((void**)&vh, g_vh);

    cudaFuncSetAttribute(mma_gemm<0>, cudaFuncAttributeMaxDynamicSharedMemorySize, GSMEM);
    cudaFuncSetAttribute(mma_gemm<1>, cudaFuncAttributeMaxDynamicSharedMemorySize, GSMEM);
    cudaFuncSetAttribute(attn_mma,    cudaFuncAttributeMaxDynamicSharedMemorySize, ASMEM);

    cvt_h2<<<(TOTAL * K_DIM / 4 + 255) / 256, 256>>>(hs, hsh, hsl, TOTAL * K_DIM / 4);
    cvt_h1<<<(N_QKV * K_DIM / 4 + 255) / 256, 256>>>(qkvw, wqh, N_QKV * K_DIM / 4);
    cvt_h1<<<(DIM * K_DIM / 4 + 255) / 256, 256>>>(projw, wph, DIM * K_DIM / 4);

    // QKV projection: Q,K -> fp32 (for RoPE), V -> fp16 directly
    mma_gemm<0><<<dim3(N_QKV / 128, TOTAL / 128), NTHR, GSMEM>>>(
        hsh, hsl, wqh, qkvb, gq, gk, vh);

    rope_cvt<<<TOTAL, 640>>>(gq, gk, cosb, sinb, qh, ql, kh);

    attn_mma<<<dim3(CHUNK / 128, HEADS, NCHUNKS), ANTHR, ASMEM>>>(
        qh, ql, kh, vh, aoh, aol);

    mma_gemm<1><<<dim3(DIM / 128, TOTAL / 128), NTHR, GSMEM>>>(
        aoh, aol, wph, projb, out,
        (float*)nullptr, (__half*)nullptr);
}

// round 15
// speedup vs baseline: 1.6576x; 1.6576x over previous
#include <cuda_runtime.h>
#include <cuda_bf16.h>
#include <cuda_fp16.h>
#include <cstdint>
#include <cstddef>

#define TOTAL   8192
#define DIM     1280
#define HEADS   16
#define HD      80
#define NCHUNKS 8
#define CHUNK   1024
#define K_DIM   1280
#define N_QKV   3840

// ---------------- scratch (device globals) ----------------------------------
__device__ float g_q [TOTAL * DIM];
__device__ float g_k [TOTAL * DIM];

__device__ __half g_hs_h[TOTAL * K_DIM];
__device__ __half g_hs_l[TOTAL * K_DIM];
__device__ __half g_wq_h[N_QKV * K_DIM];
__device__ __half g_wp_h[DIM * K_DIM];
__device__ __half g_ao_h[TOTAL * DIM];
__device__ __half g_ao_l[TOTAL * DIM];

__device__ __half g_qh[TOTAL * DIM];
__device__ __half g_ql[TOTAL * DIM];
__device__ __half g_kh[TOTAL * DIM];
__device__ __half g_vh[TOTAL * DIM];

// ---------------- PTX helpers ------------------------------------------------
__device__ __forceinline__ uint32_t smem_u32(const void* p) {
    uint32_t r;
    asm("{ .reg .u64 t; cvta.to.shared.u64 t, %1; cvt.u32.u64 %0, t; }"
        : "=r"(r) : "l"(p));
    return r;
}
__device__ __forceinline__ void cp16(uint32_t dst, const void* src) {
    asm volatile("cp.async.cg.shared.global [%0], [%1], 16;" :: "r"(dst), "l"(src));
}
__device__ __forceinline__ void ldmx4(uint32_t* a, uint32_t addr) {
    asm volatile("ldmatrix.sync.aligned.m8n8.x4.shared.b16 {%0,%1,%2,%3}, [%4];"
                 : "=r"(a[0]), "=r"(a[1]), "=r"(a[2]), "=r"(a[3]) : "r"(addr));
}
__device__ __forceinline__ void ldmx4t(uint32_t* a, uint32_t addr) {
    asm volatile("ldmatrix.sync.aligned.m8n8.x4.trans.shared.b16 {%0,%1,%2,%3}, [%4];"
                 : "=r"(a[0]), "=r"(a[1]), "=r"(a[2]), "=r"(a[3]) : "r"(addr));
}
__device__ __forceinline__ void ldmB(uint32_t* b, uint32_t addr) {
    asm volatile("ldmatrix.sync.aligned.m8n8.x2.shared.b16 {%0,%1}, [%2];"
                 : "=r"(b[0]), "=r"(b[1]) : "r"(addr));
}
// fp16 mma
__device__ __forceinline__ void mma16816h(float* d, const uint32_t* a, const uint32_t* b) {
    asm volatile(
        "mma.sync.aligned.m16n8k16.row.col.f32.f16.f16.f32 "
        "{%0,%1,%2,%3}, {%4,%5,%6,%7}, {%8,%9}, {%0,%1,%2,%3};"
        : "+f"(d[0]), "+f"(d[1]), "+f"(d[2]), "+f"(d[3])
        : "r"(a[0]), "r"(a[1]), "r"(a[2]), "r"(a[3]), "r"(b[0]), "r"(b[1]));
}
__device__ __forceinline__ float ex2(float x) {
    float r;
    asm("ex2.approx.f32 %0, %1;" : "=f"(r) : "f"(x));
    return r;
}
__device__ __forceinline__ void split2h(float a, float b, uint32_t& hi, uint32_t& lo) {
    __half2 h = __floats2half2_rn(a, b);
    float ra = a - __low2float(h);
    float rb = b - __high2float(h);
    __half2 l = __floats2half2_rn(ra, rb);
    hi = *(uint32_t*)&h;
    lo = *(uint32_t*)&l;
}
// mbarrier ops
__device__ __forceinline__ void mbar_init(uint32_t addr, uint32_t cnt) {
    asm volatile("mbarrier.init.shared.b64 [%0], %1;" :: "r"(addr), "r"(cnt) : "memory");
}
__device__ __forceinline__ void mbar_arrive(uint32_t addr) {
    asm volatile("mbarrier.arrive.shared.b64 _, [%0];" :: "r"(addr) : "memory");
}
__device__ __forceinline__ void cpasync_mbar_arrive(uint32_t addr) {
    asm volatile("cp.async.mbarrier.arrive.noinc.shared.b64 [%0];" :: "r"(addr) : "memory");
}
__device__ __forceinline__ void mbar_wait(uint32_t addr, uint32_t parity) {
    asm volatile(
        "{\n\t"
        ".reg .pred P1;\n\t"
        "WL%=:\n\t"
        "mbarrier.try_wait.parity.acquire.cta.shared::cta.b64 P1, [%0], %1, 0x989680;\n\t"
        "@P1 bra WD%=;\n\t"
        "bra WL%=;\n\t"
        "WD%=:\n\t"
        "}"
        :: "r"(addr), "r"(parity) : "memory");
}

// ---------------------------------------------------------------------------
// fp32 -> fp16 hi/lo split (activations)
// ---------------------------------------------------------------------------
__global__ void cvt_h2(const float* __restrict__ x,
                       __half* __restrict__ hi, __half* __restrict__ lo, int n4)
{
    int i = blockIdx.x * blockDim.x + threadIdx.x;
    if (i >= n4) return;
    float4 f = ((const float4*)x)[i];
    uint32_t h0, l0, h1, l1;
    split2h(f.x, f.y, h0, l0);
    split2h(f.z, f.w, h1, l1);
    ((uint32_t*)hi)[i * 2 + 0] = h0; ((uint32_t*)hi)[i * 2 + 1] = h1;
    ((uint32_t*)lo)[i * 2 + 0] = l0; ((uint32_t*)lo)[i * 2 + 1] = l1;
}

// fp32 -> fp16 (weights; single rounding)
__global__ void cvt_h1(const float* __restrict__ x, __half* __restrict__ h, int n4)
{
    int i = blockIdx.x * blockDim.x + threadIdx.x;
    if (i >= n4) return;
    float4 f = ((const float4*)x)[i];
    __half2 p0 = __floats2half2_rn(f.x, f.y);
    __half2 p1 = __floats2half2_rn(f.z, f.w);
    ((uint32_t*)h)[i * 2 + 0] = *(uint32_t*)&p0;
    ((uint32_t*)h)[i * 2 + 1] = *(uint32_t*)&p1;
}

// ---------------------------------------------------------------------------
// Warp-specialized fp16 GEMM, 2-pass: C = Ah*Bh + Al*Bh  (+ bias)
// 8 consumer warps (64x32) + 2 producer warps, 5-stage pipeline. (R13 exact)
// EPI==0: parts 0/1 (Q,K) -> fp32 O0/O1; part 2 (V) -> fp16 Ovh.
// EPI==1: fp32 store to O0.
// ---------------------------------------------------------------------------
#define KC       32
#define NCH      40
#define STRIDE   40
#define TILE_B   (128 * STRIDE * 2)    // 10240
#define STAGE_B  (3 * TILE_B)          // 30720 (Ah, Al, Bh)
#define NSTG     5
#define GSMEM    (NSTG * STAGE_B)      // 153600
#define NCONS    256
#define NPROD    64
#define NTHR     (NCONS + NPROD)

template <int EPI>
__global__ __launch_bounds__(NTHR, 1)
void mma_gemm(const __half* __restrict__ Ah, const __half* __restrict__ Al,
              const __half* __restrict__ Bh,
              const float* __restrict__ bias,
              float* __restrict__ O0, float* __restrict__ O1,
              __half* __restrict__ Ovh)
{
    extern __shared__ __half smem[];
    __shared__ __align__(8) uint64_t bar_full [NSTG];
    __shared__ __align__(8) uint64_t bar_empty[NSTG];

    const uint32_t sbase = smem_u32(smem);
    const int tid  = threadIdx.x;
    const int m0   = blockIdx.y * 128;
    const int n0   = blockIdx.x * 128;

    uint32_t full[NSTG], empty[NSTG];
#pragma unroll
    for (int s = 0; s < NSTG; s++) {
        full[s]  = smem_u32(&bar_full[s]);
        empty[s] = smem_u32(&bar_empty[s]);
    }
    if (tid == 0) {
#pragma unroll
        for (int s = 0; s < NSTG; s++) {
            mbar_init(full[s],  NPROD);
            mbar_init(empty[s], NCONS);
        }
    }
    __syncthreads();

    if (tid >= NCONS) {
        // ---------------- producer warps --------------------------------------
        const int ptid = tid - NCONS;
        const __half* srcs[3] = {
            Ah + (size_t)m0 * K_DIM, Al + (size_t)m0 * K_DIM,
            Bh + (size_t)n0 * K_DIM };
        int stage = 0, phase = 1;
        for (int ch = 0; ch < NCH; ch++) {
            mbar_wait(empty[stage], phase);
            const int k0 = ch * KC;
            const uint32_t sb = sbase + stage * STAGE_B;
#pragma unroll
            for (int t = 0; t < 24; t++) {
                int idx  = ptid + t * 64;   // 0..1535
                int tile = idx >> 9;        // 0..2
                int rem  = idx & 511;
                int row  = rem >> 2;
                int seg  = rem & 3;
                cp16(sb + tile * TILE_B + row * (STRIDE * 2) + seg * 16,
                     srcs[tile] + (size_t)row * K_DIM + k0 + seg * 8);
            }
            cpasync_mbar_arrive(full[stage]);
            if (++stage == NSTG) { stage = 0; phase ^= 1; }
        }
        return;
    }

    // ---------------- consumer warps ------------------------------------------
    const int wid  = tid >> 5;
    const int lane = tid & 31;
    const int wm   = (wid >> 2) * 64;
    const int wn   = (wid & 3) * 32;

    float acc[4][4][4];
#pragma unroll
    for (int i = 0; i < 4; i++)
#pragma unroll
        for (int j = 0; j < 4; j++)
#pragma unroll
            for (int r = 0; r < 4; r++) acc[i][j][r] = 0.f;

    const int arow  = lane & 15;
    const int acol8 = (lane >> 4) * 8;
    const int brow  = lane & 7;
    const int bcolo = ((lane >> 3) & 1) * 8;

    int stage = 0, phase = 0;
    for (int ch = 0; ch < NCH; ch++) {
        mbar_wait(full[stage], phase);

        const uint32_t sb  = sbase + stage * STAGE_B;
        const uint32_t sAh = sb;
        const uint32_t sAl = sb + TILE_B;
        const uint32_t sBh = sb + 2 * TILE_B;

#pragma unroll
        for (int kk = 0; kk < 2; kk++) {
            uint32_t aH[16], aL[16];
#pragma unroll
            for (int mt = 0; mt < 4; mt++) {
                uint32_t off = ((wm + mt * 16 + arow) * STRIDE + kk * 16 + acol8) * 2;
                ldmx4(aH + mt * 4, sAh + off);
                ldmx4(aL + mt * 4, sAl + off);
            }
#pragma unroll
            for (int nt = 0; nt < 4; nt++) {
                uint32_t bh[2];
                uint32_t off = ((wn + nt * 8 + brow) * STRIDE + kk * 16 + bcolo) * 2;
                ldmB(bh, sBh + off);
#pragma unroll
                for (int mt = 0; mt < 4; mt++) {
                    mma16816h(acc[mt][nt], aH + mt * 4, bh);
                    mma16816h(acc[mt][nt], aL + mt * 4, bh);
                }
            }
        }
        mbar_arrive(empty[stage]);
        if (++stage == NSTG) { stage = 0; phase ^= 1; }
    }

    // ---- epilogue ----
    if (EPI == 0 && n0 >= 2 * DIM) {
        // V part: single fp16 (no RoPE, consumed as B operand of PV GEMM)
        const int ccol0 = n0 - 2 * DIM;
#pragma unroll
        for (int mt = 0; mt < 4; mt++) {
#pragma unroll
            for (int nt = 0; nt < 4; nt++) {
                int row   = m0 + wm + mt * 16 + (lane >> 2);
                int bcolg = n0 + wn + nt * 8 + (lane & 3) * 2;
                int col   = ccol0 + wn + nt * 8 + (lane & 3) * 2;
                float2 bb = *(const float2*)&bias[bcolg];
                __half2 v0 = __floats2half2_rn(acc[mt][nt][0] + bb.x,
                                               acc[mt][nt][1] + bb.y);
                __half2 v1 = __floats2half2_rn(acc[mt][nt][2] + bb.x,
                                               acc[mt][nt][3] + bb.y);
                *(uint32_t*)&Ovh[(size_t)row * DIM + col]       = *(uint32_t*)&v0;
                *(uint32_t*)&Ovh[(size_t)(row + 8) * DIM + col] = *(uint32_t*)&v1;
            }
        }
    } else {
        float* dst;
        int ccol0;
        if (EPI == 0) {
            int part = n0 / DIM;
            dst   = (part == 0) ? O0 : O1;
            ccol0 = n0 - part * DIM;
        } else {
            dst   = O0;
            ccol0 = n0;
        }
#pragma unroll
        for (int mt = 0; mt < 4; mt++) {
#pragma unroll
            for (int nt = 0; nt < 4; nt++) {
                int row   = m0 + wm + mt * 16 + (lane >> 2);
                int bcolg = n0 + wn + nt * 8 + (lane & 3) * 2;
                int col   = ccol0 + wn + nt * 8 + (lane & 3) * 2;
                float2 bb = *(const float2*)&bias[bcolg];
                float2 v0, v1;
                v0.x = acc[mt][nt][0] + bb.x;  v0.y = acc[mt][nt][1] + bb.y;
                v1.x = acc[mt][nt][2] + bb.x;  v1.y = acc[mt][nt][3] + bb.y;
                *(float2*)&dst[(size_t)row * DIM + col]       = v0;
                *(float2*)&dst[(size_t)(row + 8) * DIM + col] = v1;
            }
        }
    }
}

// ---------------------------------------------------------------------------
// RoPE + scale: q -> fp16 hi/lo (scaled), k -> fp16 single
// ---------------------------------------------------------------------------
__global__ __launch_bounds__(640)
void rope_cvt(const float* __restrict__ gq, const float* __restrict__ gk,
              const float* __restrict__ cosb, const float* __restrict__ sinb,
              __half* __restrict__ qh, __half* __restrict__ ql,
              __half* __restrict__ kh)
{
    const float QSC = 0.11180339887498949f * 1.4426950408889634f;
    const int t = blockIdx.x;
    const int p = threadIdx.x;

    int h = p / 40, d = p - (p / 40) * 40;
    size_t base = (size_t)t * DIM + h * HD;
    float c0 = cosb[t * HD + d],      s0 = sinb[t * HD + d];
    float c1 = cosb[t * HD + d + 40], s1 = sinb[t * HD + d + 40];

    float a = gq[base + d], b = gq[base + d + 40];
    float q0 = (a * c0 - b * s0) * QSC;
    float q1 = (b * c1 + a * s1) * QSC;
    __half h0 = __float2half_rn(q0);
    __half h1 = __float2half_rn(q1);
    qh[base + d]      = h0;
    qh[base + d + 40] = h1;
    ql[base + d]      = __float2half_rn(q0 - __half2float(h0));
    ql[base + d + 40] = __float2half_rn(q1 - __half2float(h1));

    a = gk[base + d]; b = gk[base + d + 40];
    kh[base + d]      = __float2half_rn(a * c0 - b * s0);
    kh[base + d + 40] = __float2half_rn(b * c1 + a * s1);
}

// ---------------------------------------------------------------------------
// Flash attention on fp16 mma.sync: S = (Qh+Ql)K (2-pass), O += P V (1-pass,
// P single fp16). 8 consumer warps + 2 producer warps, 5-stage KV ring.
// ---------------------------------------------------------------------------
#define AST      88
#define ATB      (64 * AST)            // elems per buf (5632)
#define ASTAGE   (2 * ATB)             // K + V per stage (11264)
#define ANSTG    5
#define ASMEM    (ANSTG * ASTAGE * 2)  // 112640 B
#define ANCONS   256
#define ANPROD   64
#define ANTHR    (ANCONS + ANPROD)

__global__ __launch_bounds__(ANTHR, 1)
void attn_mma(const __half* __restrict__ qh, const __half* __restrict__ ql,
              const __half* __restrict__ kh, const __half* __restrict__ vh,
              __half* __restrict__ aoh, __half* __restrict__ aol)
{
    extern __shared__ __half asmem[];
    __shared__ __align__(8) uint64_t abar_full [ANSTG];
    __shared__ __align__(8) uint64_t abar_empty[ANSTG];

    const uint32_t sbase = smem_u32(asmem);
    const int tid   = threadIdx.x;
    const int chunk = blockIdx.z;
    const int head  = blockIdx.y;
    const int q0    = blockIdx.x * 128;

    uint32_t full[ANSTG], empty[ANSTG];
#pragma unroll
    for (int s = 0; s < ANSTG; s++) {
        full[s]  = smem_u32(&abar_full[s]);
        empty[s] = smem_u32(&abar_empty[s]);
    }
    if (tid == 0) {
#pragma unroll
        for (int s = 0; s < ANSTG; s++) {
            mbar_init(full[s],  ANPROD);
            mbar_init(empty[s], ANCONS);
        }
    }

    // ---- stage Q (hi/lo) through smem -----------------------------------------
    if (tid < ANCONS) {
        const __half* srcq[2] = { qh, ql };
#pragma unroll
        for (int t = 0; t < 10; t++) {
            int idx = tid + t * 256;
            int buf = idx / 1280;
            int rem = idx - buf * 1280;
            int row = rem / 10;
            int seg = rem - row * 10;
            cp16(sbase + (buf * (128 * AST) + row * AST + seg * 8) * 2,
                 srcq[buf] + (size_t)(chunk * CHUNK + q0 + row) * DIM + head * HD + seg * 8);
        }
        asm volatile("cp.async.commit_group;");
        asm volatile("cp.async.wait_group 0;");
    }
    __syncthreads();

    if (tid >= ANCONS) {
        // ---------------- producer warps ----------------------------------------
        const int ptid = tid - ANCONS;
        __syncthreads();                 // consumers finish reading Q from smem
        const __half* srckv[2] = { kh, vh };
        int st = 0, ph = 1;
        for (int t = 0; t < 16; t++) {
            mbar_wait(empty[st], ph);
            const int krow0 = chunk * CHUNK + t * 64;
            const uint32_t sb = sbase + (st * ASTAGE) * 2;
#pragma unroll
            for (int it = 0; it < 20; it++) {
                int idx = ptid + it * 64;      // 0..1279
                int buf = idx / 640;
                int rem = idx - buf * 640;
                int row = rem / 10;
                int seg = rem - row * 10;
                cp16(sb + (buf * ATB + row * AST + seg * 8) * 2,
                     srckv[buf] + (size_t)(krow0 + row) * DIM + head * HD + seg * 8);
            }
            cpasync_mbar_arrive(full[st]);
            if (++st == ANSTG) { st = 0; ph ^= 1; }
        }
        return;
    }

    // ---------------- consumer warps --------------------------------------------
    const int wid  = tid >> 5;
    const int lane = tid & 31;
    const int wm   = wid * 16;

    uint32_t aQh[5][4], aQl[5][4];
    {
        const int arow = lane & 15;
        const int acol8 = 8 * (lane >> 4);
#pragma unroll
        for (int ks = 0; ks < 5; ks++) {
            uint32_t off = ((wm + arow) * AST + ks * 16 + acol8) * 2;
            ldmx4(aQh[ks], sbase + off);
            ldmx4(aQl[ks], sbase + (128 * AST) * 2 + off);
        }
    }
    __syncthreads();   // release smem to producers

    float o[10][4];
#pragma unroll
    for (int i = 0; i < 10; i++)
#pragma unroll
        for (int r = 0; r < 4; r++) o[i][r] = 0.f;
    float mrow0 = -1e30f, mrow1 = -1e30f, lrow0 = 0.f, lrow1 = 0.f;

    int st = 0, ph = 0;
    for (int t = 0; t < 16; t++) {
        mbar_wait(full[st], ph);

        const uint32_t sb = sbase + (st * ASTAGE) * 2;
        const uint32_t sK = sb;
        const uint32_t sV = sb + ATB * 2;

        // ---- S = Q K^T (2 passes) -----------------------------------------------
        float S[8][4];
#pragma unroll
        for (int f = 0; f < 8; f++)
#pragma unroll
            for (int r = 0; r < 4; r++) S[f][r] = 0.f;

#pragma unroll
        for (int ks = 0; ks < 5; ks++) {
#pragma unroll
            for (int ng = 0; ng < 4; ng++) {
                uint32_t bh[4];
                uint32_t off = ((ng * 16 + 8 * (lane >> 4) + (lane & 7)) * AST
                                + ks * 16 + 8 * ((lane >> 3) & 1)) * 2;
                ldmx4(bh, sK + off);
                mma16816h(S[2 * ng],     aQh[ks], bh);
                mma16816h(S[2 * ng],     aQl[ks], bh);
                mma16816h(S[2 * ng + 1], aQh[ks], bh + 2);
                mma16816h(S[2 * ng + 1], aQl[ks], bh + 2);
            }
        }

        // ---- online softmax (base 2) --------------------------------------------
        float mx0 = S[0][0], mx1 = S[0][2];
#pragma unroll
        for (int f = 0; f < 8; f++) {
            mx0 = fmaxf(mx0, fmaxf(S[f][0], S[f][1]));
            mx1 = fmaxf(mx1, fmaxf(S[f][2], S[f][3]));
        }
        mx0 = fmaxf(mx0, __shfl_xor_sync(0xffffffff, mx0, 1));
        mx0 = fmaxf(mx0, __shfl_xor_sync(0xffffffff, mx0, 2));
        mx1 = fmaxf(mx1, __shfl_xor_sync(0xffffffff, mx1, 1));
        mx1 = fmaxf(mx1, __shfl_xor_sync(0xffffffff, mx1, 2));

        float mn0 = fmaxf(mrow0, mx0), mn1 = fmaxf(mrow1, mx1);
        float al0 = ex2(mrow0 - mn0),  al1 = ex2(mrow1 - mn1);
        mrow0 = mn0; mrow1 = mn1;
#pragma unroll
        for (int i = 0; i < 10; i++) {
            o[i][0] *= al0; o[i][1] *= al0;
            o[i][2] *= al1; o[i][3] *= al1;
        }
        float rs0 = 0.f, rs1 = 0.f;
#pragma unroll
        for (int f = 0; f < 8; f++) {
            S[f][0] = ex2(S[f][0] - mn0); rs0 += S[f][0];
            S[f][1] = ex2(S[f][1] - mn0); rs0 += S[f][1];
            S[f][2] = ex2(S[f][2] - mn1); rs1 += S[f][2];
            S[f][3] = ex2(S[f][3] - mn1); rs1 += S[f][3];
        }
        rs0 += __shfl_xor_sync(0xffffffff, rs0, 1);
        rs0 += __shfl_xor_sync(0xffffffff, rs0, 2);
        rs1 += __shfl_xor_sync(0xffffffff, rs1, 1);
        rs1 += __shfl_xor_sync(0xffffffff, rs1, 2);
        lrow0 = lrow0 * al0 + rs0;
        lrow1 = lrow1 * al1 + rs1;

        // ---- P (single fp16 a-frags) ----------------------------------------------
        uint32_t pH[4][4];
#pragma unroll
        for (int j = 0; j < 4; j++) {
            __half2 p0 = __floats2half2_rn(S[2 * j][0],     S[2 * j][1]);
            __half2 p1 = __floats2half2_rn(S[2 * j][2],     S[2 * j][3]);
            __half2 p2 = __floats2half2_rn(S[2 * j + 1][0], S[2 * j + 1][1]);
            __half2 p3 = __floats2half2_rn(S[2 * j + 1][2], S[2 * j + 1][3]);
            pH[j][0] = *(uint32_t*)&p0;
            pH[j][1] = *(uint32_t*)&p1;
            pH[j][2] = *(uint32_t*)&p2;
            pH[j][3] = *(uint32_t*)&p3;
        }

        // ---- O += P V (1 pass) -------------------------------------------------------
#pragma unroll
        for (int j = 0; j < 4; j++) {
#pragma unroll
            for (int ng = 0; ng < 5; ng++) {
                uint32_t bv[4];
                uint32_t off = ((j * 16 + (lane & 15)) * AST
                                + ng * 16 + 8 * (lane >> 4)) * 2;
                ldmx4t(bv, sV + off);
                mma16816h(o[2 * ng],     pH[j], bv);
                mma16816h(o[2 * ng + 1], pH[j], bv + 2);
            }
        }
        mbar_arrive(empty[st]);
        if (++st == ANSTG) { st = 0; ph ^= 1; }
    }

    // ---- normalize + store fp16 hi/lo (for proj GEMM) -------------------------
    float inv0 = 1.f / lrow0, inv1 = 1.f / lrow1;
    const int row0 = chunk * CHUNK + q0 + wm + (lane >> 2);
    const int col0 = head * HD + 2 * (lane & 3);
#pragma unroll
    for (int nt = 0; nt < 10; nt++) {
        uint32_t hi, lo;
        size_t idx0 = (size_t)row0 * DIM + col0 + nt * 8;
        split2h(o[nt][0] * inv0, o[nt][1] * inv0, hi, lo);
        *(uint32_t*)&aoh[idx0] = hi;
        *(uint32_t*)&aol[idx0] = lo;
        size_t idx1 = (size_t)(row0 + 8) * DIM + col0 + nt * 8;
        split2h(o[nt][2] * inv1, o[nt][3] * inv1, hi, lo);
        *(uint32_t*)&aoh[idx1] = hi;
        *(uint32_t*)&aol[idx1] = lo;
    }
}

// ---------------------------------------------------------------------------
// Launch
// ---------------------------------------------------------------------------
extern "C" void kernel_launch(void* const* d_in, const int* in_sizes, int n_in,
                              void* d_out, int out_size)
{
    const float* hs    = (const float*)d_in[0];
    const float* cosb  = (const float*)d_in[1];
    const float* sinb  = (const float*)d_in[2];
    const float* qkvw  = (const float*)d_in[3];
    const float* qkvb  = (const float*)d_in[4];
    const float* projw = (const float*)d_in[5];
    const float* projb = (const float*)d_in[6];
    float* out = (float*)d_out;
    (void)in_sizes; (void)n_in; (void)out_size;

    float *gq, *gk;
    cudaGetSymbolAddress((void**)&gq, g_q);
    cudaGetSymbolAddress((void**)&gk, g_k);

    __half *hsh, *hsl, *wqh, *wph, *aoh, *aol, *qh, *ql, *kh, *vh;
    cudaGetSymbolAddress((void**)&hsh, g_hs_h);
    cudaGetSymbolAddress((void**)&hsl, g_hs_l);
    cudaGetSymbolAddress((void**)&wqh, g_wq_h);
    cudaGetSymbolAddress((void**)&wph, g_wp_h);
    cudaGetSymbolAddress((void**)&aoh, g_ao_h);
    cudaGetSymbolAddress((void**)&aol, g_ao_l);
    cudaGetSymbolAddress((void**)&qh, g_qh);
    cudaGetSymbolAddress((void**)&ql, g_ql);
    cudaGetSymbolAddress((void**)&kh, g_kh);
    cudaGetSymbolAddress((void**)&vh, g_vh);

    cudaFuncSetAttribute(mma_gemm<0>, cudaFuncAttributeMaxDynamicSharedMemorySize, GSMEM);
    cudaFuncSetAttribute(mma_gemm<1>, cudaFuncAttributeMaxDynamicSharedMemorySize, GSMEM);
    cudaFuncSetAttribute(attn_mma,    cudaFuncAttributeMaxDynamicSharedMemorySize, ASMEM);

    cvt_h2<<<(TOTAL * K_DIM / 4 + 255) / 256, 256>>>(hs, hsh, hsl, TOTAL * K_DIM / 4);
    cvt_h1<<<(N_QKV * K_DIM / 4 + 255) / 256, 256>>>(qkvw, wqh, N_QKV * K_DIM / 4);
    cvt_h1<<<(DIM * K_DIM / 4 + 255) / 256, 256>>>(projw, wph, DIM * K_DIM / 4);

    // QKV projection: Q,K -> fp32 (for RoPE), V -> fp16 directly
    mma_gemm<0><<<dim3(N_QKV / 128, TOTAL / 128), NTHR, GSMEM>>>(
        hsh, hsl, wqh, qkvb, gq, gk, vh);

    rope_cvt<<<TOTAL, 640>>>(gq, gk, cosb, sinb, qh, ql, kh);

    attn_mma<<<dim3(CHUNK / 128, HEADS, NCHUNKS), ANTHR, ASMEM>>>(
        qh, ql, kh, vh, aoh, aol);

    mma_gemm<1><<<dim3(DIM / 128, TOTAL / 128), NTHR, GSMEM>>>(
        aoh, aol, wph, projb, out,
        (float*)nullptr, (__half*)nullptr);
}

// round 16
// speedup vs baseline: 2.4123x; 1.4553x over previous
#include <cuda_runtime.h>
#include <cuda_bf16.h>
#include <cuda_fp16.h>
#include <cstdint>
#include <cstddef>

#define TOTAL   8192
#define DIM     1280
#define HEADS   16
#define HD      80
#define NCHUNKS 8
#define CHUNK   1024
#define K_DIM   1280
#define N_QKV   3840

// ---------------- scratch (device globals) ----------------------------------
__device__ float g_q [TOTAL * DIM];
__device__ float g_k [TOTAL * DIM];

__device__ __half g_hs_h[TOTAL * K_DIM];
__device__ __half g_wq_h[N_QKV * K_DIM];
__device__ __half g_wp_h[DIM * K_DIM];
__device__ __half g_ao_h[TOTAL * DIM];

__device__ __half g_qh[TOTAL * DIM];
__device__ __half g_ql[TOTAL * DIM];
__device__ __half g_kh[TOTAL * DIM];
__device__ __half g_vh[TOTAL * DIM];

// ---------------- PTX helpers ------------------------------------------------
__device__ __forceinline__ uint32_t smem_u32(const void* p) {
    uint32_t r;
    asm("{ .reg .u64 t; cvta.to.shared.u64 t, %1; cvt.u32.u64 %0, t; }"
        : "=r"(r) : "l"(p));
    return r;
}
__device__ __forceinline__ void cp16(uint32_t dst, const void* src) {
    asm volatile("cp.async.cg.shared.global [%0], [%1], 16;" :: "r"(dst), "l"(src));
}
__device__ __forceinline__ void ldmx4(uint32_t* a, uint32_t addr) {
    asm volatile("ldmatrix.sync.aligned.m8n8.x4.shared.b16 {%0,%1,%2,%3}, [%4];"
                 : "=r"(a[0]), "=r"(a[1]), "=r"(a[2]), "=r"(a[3]) : "r"(addr));
}
__device__ __forceinline__ void ldmx4t(uint32_t* a, uint32_t addr) {
    asm volatile("ldmatrix.sync.aligned.m8n8.x4.trans.shared.b16 {%0,%1,%2,%3}, [%4];"
                 : "=r"(a[0]), "=r"(a[1]), "=r"(a[2]), "=r"(a[3]) : "r"(addr));
}
__device__ __forceinline__ void ldmB(uint32_t* b, uint32_t addr) {
    asm volatile("ldmatrix.sync.aligned.m8n8.x2.shared.b16 {%0,%1}, [%2];"
                 : "=r"(b[0]), "=r"(b[1]) : "r"(addr));
}
// fp16 mma
__device__ __forceinline__ void mma16816h(float* d, const uint32_t* a, const uint32_t* b) {
    asm volatile(
        "mma.sync.aligned.m16n8k16.row.col.f32.f16.f16.f32 "
        "{%0,%1,%2,%3}, {%4,%5,%6,%7}, {%8,%9}, {%0,%1,%2,%3};"
        : "+f"(d[0]), "+f"(d[1]), "+f"(d[2]), "+f"(d[3])
        : "r"(a[0]), "r"(a[1]), "r"(a[2]), "r"(a[3]), "r"(b[0]), "r"(b[1]));
}
__device__ __forceinline__ float ex2(float x) {
    float r;
    asm("ex2.approx.f32 %0, %1;" : "=f"(r) : "f"(x));
    return r;
}
__device__ __forceinline__ void split2h(float a, float b, uint32_t& hi, uint32_t& lo) {
    __half2 h = __floats2half2_rn(a, b);
    float ra = a - __low2float(h);
    float rb = b - __high2float(h);
    __half2 l = __floats2half2_rn(ra, rb);
    hi = *(uint32_t*)&h;
    lo = *(uint32_t*)&l;
}
// mbarrier ops
__device__ __forceinline__ void mbar_init(uint32_t addr, uint32_t cnt) {
    asm volatile("mbarrier.init.shared.b64 [%0], %1;" :: "r"(addr), "r"(cnt) : "memory");
}
__device__ __forceinline__ void mbar_arrive(uint32_t addr) {
    asm volatile("mbarrier.arrive.shared.b64 _, [%0];" :: "r"(addr) : "memory");
}
__device__ __forceinline__ void cpasync_mbar_arrive(uint32_t addr) {
    asm volatile("cp.async.mbarrier.arrive.noinc.shared.b64 [%0];" :: "r"(addr) : "memory");
}
__device__ __forceinline__ void mbar_wait(uint32_t addr, uint32_t parity) {
    asm volatile(
        "{\n\t"
        ".reg .pred P1;\n\t"
        "WL%=:\n\t"
        "mbarrier.try_wait.parity.acquire.cta.shared::cta.b64 P1, [%0], %1, 0x989680;\n\t"
        "@P1 bra WD%=;\n\t"
        "bra WL%=;\n\t"
        "WD%=:\n\t"
        "}"
        :: "r"(addr), "r"(parity) : "memory");
}

// ---------------------------------------------------------------------------
// fp32 -> fp16 (single rounding)
// ---------------------------------------------------------------------------
__global__ void cvt_h1(const float* __restrict__ x, __half* __restrict__ h, int n4)
{
    int i = blockIdx.x * blockDim.x + threadIdx.x;
    if (i >= n4) return;
    float4 f = ((const float4*)x)[i];
    __half2 p0 = __floats2half2_rn(f.x, f.y);
    __half2 p1 = __floats2half2_rn(f.z, f.w);
    ((uint32_t*)h)[i * 2 + 0] = *(uint32_t*)&p0;
    ((uint32_t*)h)[i * 2 + 1] = *(uint32_t*)&p1;
}

// ---------------------------------------------------------------------------
// Warp-specialized fp16 GEMM, single-pass: C = A*B + bias
// 8 consumer warps (64x32) + 2 producer warps, 5-stage pipeline.
// EPI==0: parts 0/1 (Q,K) -> fp32 O0/O1; part 2 (V) -> fp16 Ovh.
// EPI==1: fp32 store to O0.
// ---------------------------------------------------------------------------
#define KC       32
#define NCH      40
#define STRIDE   40
#define TILE_B   (128 * STRIDE * 2)    // 10240
#define STAGE_B  (2 * TILE_B)          // 20480 (A, B)
#define NSTG     5
#define GSMEM    (NSTG * STAGE_B)      // 102400
#define NCONS    256
#define NPROD    64
#define NTHR     (NCONS + NPROD)

template <int EPI>
__global__ __launch_bounds__(NTHR, 1)
void mma_gemm(const __half* __restrict__ A, const __half* __restrict__ B,
              const float* __restrict__ bias,
              float* __restrict__ O0, float* __restrict__ O1,
              __half* __restrict__ Ovh)
{
    extern __shared__ __half smem[];
    __shared__ __align__(8) uint64_t bar_full [NSTG];
    __shared__ __align__(8) uint64_t bar_empty[NSTG];

    const uint32_t sbase = smem_u32(smem);
    const int tid  = threadIdx.x;
    const int m0   = blockIdx.y * 128;
    const int n0   = blockIdx.x * 128;

    uint32_t full[NSTG], empty[NSTG];
#pragma unroll
    for (int s = 0; s < NSTG; s++) {
        full[s]  = smem_u32(&bar_full[s]);
        empty[s] = smem_u32(&bar_empty[s]);
    }
    if (tid == 0) {
#pragma unroll
        for (int s = 0; s < NSTG; s++) {
            mbar_init(full[s],  NPROD);
            mbar_init(empty[s], NCONS);
        }
    }
    __syncthreads();

    if (tid >= NCONS) {
        // ---------------- producer warps --------------------------------------
        const int ptid = tid - NCONS;    // 0..63
        const __half* srcs[2] = {
            A + (size_t)m0 * K_DIM, B + (size_t)n0 * K_DIM };
        int stage = 0, phase = 1;
        for (int ch = 0; ch < NCH; ch++) {
            mbar_wait(empty[stage], phase);
            const int k0 = ch * KC;
            const uint32_t sb = sbase + stage * STAGE_B;
#pragma unroll
            for (int t = 0; t < 16; t++) {
                int idx  = ptid + t * 64;   // 0..1023
                int tile = idx >> 9;        // 0..1
                int rem  = idx & 511;
                int row  = rem >> 2;
                int seg  = rem & 3;
                cp16(sb + tile * TILE_B + row * (STRIDE * 2) + seg * 16,
                     srcs[tile] + (size_t)row * K_DIM + k0 + seg * 8);
            }
            cpasync_mbar_arrive(full[stage]);
            if (++stage == NSTG) { stage = 0; phase ^= 1; }
        }
        return;
    }

    // ---------------- consumer warps ------------------------------------------
    const int wid  = tid >> 5;
    const int lane = tid & 31;
    const int wm   = (wid >> 2) * 64;
    const int wn   = (wid & 3) * 32;

    float acc[4][4][4];
#pragma unroll
    for (int i = 0; i < 4; i++)
#pragma unroll
        for (int j = 0; j < 4; j++)
#pragma unroll
            for (int r = 0; r < 4; r++) acc[i][j][r] = 0.f;

    const int arow  = lane & 15;
    const int acol8 = (lane >> 4) * 8;
    const int brow  = lane & 7;
    const int bcolo = ((lane >> 3) & 1) * 8;

    int stage = 0, phase = 0;
    for (int ch = 0; ch < NCH; ch++) {
        mbar_wait(full[stage], phase);

        const uint32_t sb = sbase + stage * STAGE_B;
        const uint32_t sA = sb;
        const uint32_t sB = sb + TILE_B;

#pragma unroll
        for (int kk = 0; kk < 2; kk++) {
            uint32_t aH[16];
#pragma unroll
            for (int mt = 0; mt < 4; mt++) {
                uint32_t off = ((wm + mt * 16 + arow) * STRIDE + kk * 16 + acol8) * 2;
                ldmx4(aH + mt * 4, sA + off);
            }
#pragma unroll
            for (int nt = 0; nt < 4; nt++) {
                uint32_t bh[2];
                uint32_t off = ((wn + nt * 8 + brow) * STRIDE + kk * 16 + bcolo) * 2;
                ldmB(bh, sB + off);
#pragma unroll
                for (int mt = 0; mt < 4; mt++)
                    mma16816h(acc[mt][nt], aH + mt * 4, bh);
            }
        }
        mbar_arrive(empty[stage]);
        if (++stage == NSTG) { stage = 0; phase ^= 1; }
    }

    // ---- epilogue ----
    if (EPI == 0 && n0 >= 2 * DIM) {
        // V part: single fp16
        const int ccol0 = n0 - 2 * DIM;
#pragma unroll
        for (int mt = 0; mt < 4; mt++) {
#pragma unroll
            for (int nt = 0; nt < 4; nt++) {
                int row   = m0 + wm + mt * 16 + (lane >> 2);
                int bcolg = n0 + wn + nt * 8 + (lane & 3) * 2;
                int col   = ccol0 + wn + nt * 8 + (lane & 3) * 2;
                float2 bb = *(const float2*)&bias[bcolg];
                __half2 v0 = __floats2half2_rn(acc[mt][nt][0] + bb.x,
                                               acc[mt][nt][1] + bb.y);
                __half2 v1 = __floats2half2_rn(acc[mt][nt][2] + bb.x,
                                               acc[mt][nt][3] + bb.y);
                *(uint32_t*)&Ovh[(size_t)row * DIM + col]       = *(uint32_t*)&v0;
                *(uint32_t*)&Ovh[(size_t)(row + 8) * DIM + col] = *(uint32_t*)&v1;
            }
        }
    } else {
        float* dst;
        int ccol0;
        if (EPI == 0) {
            int part = n0 / DIM;
            dst   = (part == 0) ? O0 : O1;
            ccol0 = n0 - part * DIM;
        } else {
            dst   = O0;
            ccol0 = n0;
        }
#pragma unroll
        for (int mt = 0; mt < 4; mt++) {
#pragma unroll
            for (int nt = 0; nt < 4; nt++) {
                int row   = m0 + wm + mt * 16 + (lane >> 2);
                int bcolg = n0 + wn + nt * 8 + (lane & 3) * 2;
                int col   = ccol0 + wn + nt * 8 + (lane & 3) * 2;
                float2 bb = *(const float2*)&bias[bcolg];
                float2 v0, v1;
                v0.x = acc[mt][nt][0] + bb.x;  v0.y = acc[mt][nt][1] + bb.y;
                v1.x = acc[mt][nt][2] + bb.x;  v1.y = acc[mt][nt][3] + bb.y;
                *(float2*)&dst[(size_t)row * DIM + col]       = v0;
                *(float2*)&dst[(size_t)(row + 8) * DIM + col] = v1;
            }
        }
    }
}

// ---------------------------------------------------------------------------
// RoPE + scale: q -> fp16 hi/lo (scaled), k -> fp16 single
// ---------------------------------------------------------------------------
__global__ __launch_bounds__(640)
void rope_cvt(const float* __restrict__ gq, const float* __restrict__ gk,
              const float* __restrict__ cosb, const float* __restrict__ sinb,
              __half* __restrict__ qh, __half* __restrict__ ql,
              __half* __restrict__ kh)
{
    const float QSC = 0.11180339887498949f * 1.4426950408889634f;
    const int t = blockIdx.x;
    const int p = threadIdx.x;

    int h = p / 40, d = p - (p / 40) * 40;
    size_t base = (size_t)t * DIM + h * HD;
    float c0 = cosb[t * HD + d],      s0 = sinb[t * HD + d];
    float c1 = cosb[t * HD + d + 40], s1 = sinb[t * HD + d + 40];

    float a = gq[base + d], b = gq[base + d + 40];
    float q0 = (a * c0 - b * s0) * QSC;
    float q1 = (b * c1 + a * s1) * QSC;
    __half h0 = __float2half_rn(q0);
    __half h1 = __float2half_rn(q1);
    qh[base + d]      = h0;
    qh[base + d + 40] = h1;
    ql[base + d]      = __float2half_rn(q0 - __half2float(h0));
    ql[base + d + 40] = __float2half_rn(q1 - __half2float(h1));

    a = gk[base + d]; b = gk[base + d + 40];
    kh[base + d]      = __float2half_rn(a * c0 - b * s0);
    kh[base + d + 40] = __float2half_rn(b * c1 + a * s1);
}

// ---------------------------------------------------------------------------
// Flash attention on fp16 mma.sync: S = (Qh+Ql)K (2-pass), O += P V (1-pass).
// 8 consumer warps + 2 producer warps, 5-stage KV ring. Output single fp16.
// ---------------------------------------------------------------------------
#define AST      88
#define ATB      (64 * AST)
#define ASTAGE   (2 * ATB)
#define ANSTG    5
#define ASMEM    (ANSTG * ASTAGE * 2)  // 112640 B
#define ANCONS   256
#define ANPROD   64
#define ANTHR    (ANCONS + ANPROD)

__global__ __launch_bounds__(ANTHR, 1)
void attn_mma(const __half* __restrict__ qh, const __half* __restrict__ ql,
              const __half* __restrict__ kh, const __half* __restrict__ vh,
              __half* __restrict__ aoh)
{
    extern __shared__ __half asmem[];
    __shared__ __align__(8) uint64_t abar_full [ANSTG];
    __shared__ __align__(8) uint64_t abar_empty[ANSTG];

    const uint32_t sbase = smem_u32(asmem);
    const int tid   = threadIdx.x;
    const int chunk = blockIdx.z;
    const int head  = blockIdx.y;
    const int q0    = blockIdx.x * 128;

    uint32_t full[ANSTG], empty[ANSTG];
#pragma unroll
    for (int s = 0; s < ANSTG; s++) {
        full[s]  = smem_u32(&abar_full[s]);
        empty[s] = smem_u32(&abar_empty[s]);
    }
    if (tid == 0) {
#pragma unroll
        for (int s = 0; s < ANSTG; s++) {
            mbar_init(full[s],  ANPROD);
            mbar_init(empty[s], ANCONS);
        }
    }

    // ---- stage Q (hi/lo) through smem -----------------------------------------
    if (tid < ANCONS) {
        const __half* srcq[2] = { qh, ql };
#pragma unroll
        for (int t = 0; t < 10; t++) {
            int idx = tid + t * 256;
            int buf = idx / 1280;
            int rem = idx - buf * 1280;
            int row = rem / 10;
            int seg = rem - row * 10;
            cp16(sbase + (buf * (128 * AST) + row * AST + seg * 8) * 2,
                 srcq[buf] + (size_t)(chunk * CHUNK + q0 + row) * DIM + head * HD + seg * 8);
        }
        asm volatile("cp.async.commit_group;");
        asm volatile("cp.async.wait_group 0;");
    }
    __syncthreads();

    if (tid >= ANCONS) {
        // ---------------- producer warps ----------------------------------------
        const int ptid = tid - ANCONS;
        __syncthreads();                 // consumers finish reading Q from smem
        const __half* srckv[2] = { kh, vh };
        int st = 0, ph = 1;
        for (int t = 0; t < 16; t++) {
            mbar_wait(empty[st], ph);
            const int krow0 = chunk * CHUNK + t * 64;
            const uint32_t sb = sbase + (st * ASTAGE) * 2;
#pragma unroll
            for (int it = 0; it < 20; it++) {
                int idx = ptid + it * 64;
                int buf = idx / 640;
                int rem = idx - buf * 640;
                int row = rem / 10;
                int seg = rem - row * 10;
                cp16(sb + (buf * ATB + row * AST + seg * 8) * 2,
                     srckv[buf] + (size_t)(krow0 + row) * DIM + head * HD + seg * 8);
            }
            cpasync_mbar_arrive(full[st]);
            if (++st == ANSTG) { st = 0; ph ^= 1; }
        }
        return;
    }

    // ---------------- consumer warps --------------------------------------------
    const int wid  = tid >> 5;
    const int lane = tid & 31;
    const int wm   = wid * 16;

    uint32_t aQh[5][4], aQl[5][4];
    {
        const int arow = lane & 15;
        const int acol8 = 8 * (lane >> 4);
#pragma unroll
        for (int ks = 0; ks < 5; ks++) {
            uint32_t off = ((wm + arow) * AST + ks * 16 + acol8) * 2;
            ldmx4(aQh[ks], sbase + off);
            ldmx4(aQl[ks], sbase + (128 * AST) * 2 + off);
        }
    }
    __syncthreads();   // release smem to producers

    float o[10][4];
#pragma unroll
    for (int i = 0; i < 10; i++)
#pragma unroll
        for (int r = 0; r < 4; r++) o[i][r] = 0.f;
    float mrow0 = -1e30f, mrow1 = -1e30f, lrow0 = 0.f, lrow1 = 0.f;

    int st = 0, ph = 0;
    for (int t = 0; t < 16; t++) {
        mbar_wait(full[st], ph);

        const uint32_t sb = sbase + (st * ASTAGE) * 2;
        const uint32_t sK = sb;
        const uint32_t sV = sb + ATB * 2;

        // ---- S = Q K^T (2 passes) -----------------------------------------------
        float S[8][4];
#pragma unroll
        for (int f = 0; f < 8; f++)
#pragma unroll
            for (int r = 0; r < 4; r++) S[f][r] = 0.f;

#pragma unroll
        for (int ks = 0; ks < 5; ks++) {
#pragma unroll
            for (int ng = 0; ng < 4; ng++) {
                uint32_t bh[4];
                uint32_t off = ((ng * 16 + 8 * (lane >> 4) + (lane & 7)) * AST
                                + ks * 16 + 8 * ((lane >> 3) & 1)) * 2;
                ldmx4(bh, sK + off);
                mma16816h(S[2 * ng],     aQh[ks], bh);
                mma16816h(S[2 * ng],     aQl[ks], bh);
                mma16816h(S[2 * ng + 1], aQh[ks], bh + 2);
                mma16816h(S[2 * ng + 1], aQl[ks], bh + 2);
            }
        }

        // ---- online softmax (base 2) --------------------------------------------
        float mx0 = S[0][0], mx1 = S[0][2];
#pragma unroll
        for (int f = 0; f < 8; f++) {
            mx0 = fmaxf(mx0, fmaxf(S[f][0], S[f][1]));
            mx1 = fmaxf(mx1, fmaxf(S[f][2], S[f][3]));
        }
        mx0 = fmaxf(mx0, __shfl_xor_sync(0xffffffff, mx0, 1));
        mx0 = fmaxf(mx0, __shfl_xor_sync(0xffffffff, mx0, 2));
        mx1 = fmaxf(mx1, __shfl_xor_sync(0xffffffff, mx1, 1));
        mx1 = fmaxf(mx1, __shfl_xor_sync(0xffffffff, mx1, 2));

        float mn0 = fmaxf(mrow0, mx0), mn1 = fmaxf(mrow1, mx1);
        float al0 = ex2(mrow0 - mn0),  al1 = ex2(mrow1 - mn1);
        mrow0 = mn0; mrow1 = mn1;
#pragma unroll
        for (int i = 0; i < 10; i++) {
            o[i][0] *= al0; o[i][1] *= al0;
            o[i][2] *= al1; o[i][3] *= al1;
        }
        float rs0 = 0.f, rs1 = 0.f;
#pragma unroll
        for (int f = 0; f < 8; f++) {
            S[f][0] = ex2(S[f][0] - mn0); rs0 += S[f][0];
            S[f][1] = ex2(S[f][1] - mn0); rs0 += S[f][1];
            S[f][2] = ex2(S[f][2] - mn1); rs1 += S[f][2];
            S[f][3] = ex2(S[f][3] - mn1); rs1 += S[f][3];
        }
        rs0 += __shfl_xor_sync(0xffffffff, rs0, 1);
        rs0 += __shfl_xor_sync(0xffffffff, rs0, 2);
        rs1 += __shfl_xor_sync(0xffffffff, rs1, 1);
        rs1 += __shfl_xor_sync(0xffffffff, rs1, 2);
        lrow0 = lrow0 * al0 + rs0;
        lrow1 = lrow1 * al1 + rs1;

        // ---- P (single fp16 a-frags) ----------------------------------------------
        uint32_t pH[4][4];
#pragma unroll
        for (int j = 0; j < 4; j++) {
            __half2 p0 = __floats2half2_rn(S[2 * j][0],     S[2 * j][1]);
            __half2 p1 = __floats2half2_rn(S[2 * j][2],     S[2 * j][3]);
            __half2 p2 = __floats2half2_rn(S[2 * j + 1][0], S[2 * j + 1][1]);
            __half2 p3 = __floats2half2_rn(S[2 * j + 1][2], S[2 * j + 1][3]);
            pH[j][0] = *(uint32_t*)&p0;
            pH[j][1] = *(uint32_t*)&p1;
            pH[j][2] = *(uint32_t*)&p2;
            pH[j][3] = *(uint32_t*)&p3;
        }

        // ---- O += P V (1 pass) -------------------------------------------------------
#pragma unroll
        for (int j = 0; j < 4; j++) {
#pragma unroll
            for (int ng = 0; ng < 5; ng++) {
                uint32_t bv[4];
                uint32_t off = ((j * 16 + (lane & 15)) * AST
                                + ng * 16 + 8 * (lane >> 4)) * 2;
                ldmx4t(bv, sV + off);
                mma16816h(o[2 * ng],     pH[j], bv);
                mma16816h(o[2 * ng + 1], pH[j], bv + 2);
            }
        }
        mbar_arrive(empty[st]);
        if (++st == ANSTG) { st = 0; ph ^= 1; }
    }

    // ---- normalize + store single fp16 (for single-pass proj GEMM) ------------
    float inv0 = 1.f / lrow0, inv1 = 1.f / lrow1;
    const int row0 = chunk * CHUNK + q0 + wm + (lane >> 2);
    const int col0 = head * HD + 2 * (lane & 3);
#pragma unroll
    for (int nt = 0; nt < 10; nt++) {
        size_t idx0 = (size_t)row0 * DIM + col0 + nt * 8;
        __half2 v0 = __floats2half2_rn(o[nt][0] * inv0, o[nt][1] * inv0);
        *(uint32_t*)&aoh[idx0] = *(uint32_t*)&v0;
        size_t idx1 = (size_t)(row0 + 8) * DIM + col0 + nt * 8;
        __half2 v1 = __floats2half2_rn(o[nt][2] * inv1, o[nt][3] * inv1);
        *(uint32_t*)&aoh[idx1] = *(uint32_t*)&v1;
    }
}

// ---------------------------------------------------------------------------
// Launch
// ---------------------------------------------------------------------------
extern "C" void kernel_launch(void* const* d_in, const int* in_sizes, int n_in,
                              void* d_out, int out_size)
{
    const float* hs    = (const float*)d_in[0];
    const float* cosb  = (const float*)d_in[1];
    const float* sinb  = (const float*)d_in[2];
    const float* qkvw  = (const float*)d_in[3];
    const float* qkvb  = (const float*)d_in[4];
    const float* projw = (const float*)d_in[5];
    const float* projb = (const float*)d_in[6];
    float* out = (float*)d_out;
    (void)in_sizes; (void)n_in; (void)out_size;

    float *gq, *gk;
    cudaGetSymbolAddress((void**)&gq, g_q);
    cudaGetSymbolAddress((void**)&gk, g_k);

    __half *hsh, *wqh, *wph, *aoh, *qh, *ql, *kh, *vh;
    cudaGetSymbolAddress((void**)&hsh, g_hs_h);
    cudaGetSymbolAddress((void**)&wqh, g_wq_h);
    cudaGetSymbolAddress((void**)&wph, g_wp_h);
    cudaGetSymbolAddress((void**)&aoh, g_ao_h);
    cudaGetSymbolAddress((void**)&qh, g_qh);
    cudaGetSymbolAddress((void**)&ql, g_ql);
    cudaGetSymbolAddress((void**)&kh, g_kh);
    cudaGetSymbolAddress((void**)&vh, g_vh);

    cudaFuncSetAttribute(mma_gemm<0>, cudaFuncAttributeMaxDynamicSharedMemorySize, GSMEM);
    cudaFuncSetAttribute(mma_gemm<1>, cudaFuncAttributeMaxDynamicSharedMemorySize, GSMEM);
    cudaFuncSetAttribute(attn_mma,    cudaFuncAttributeMaxDynamicSharedMemorySize, ASMEM);

    cvt_h1<<<(TOTAL * K_DIM / 4 + 255) / 256, 256>>>(hs, hsh, TOTAL * K_DIM / 4);
    cvt_h1<<<(N_QKV * K_DIM / 4 + 255) / 256, 256>>>(qkvw, wqh, N_QKV * K_DIM / 4);
    cvt_h1<<<(DIM * K_DIM / 4 + 255) / 256, 256>>>(projw, wph, DIM * K_DIM / 4);

    // QKV projection: Q,K -> fp32 (for RoPE), V -> fp16 directly
    mma_gemm<0><<<dim3(N_QKV / 128, TOTAL / 128), NTHR, GSMEM>>>(
        hsh, wqh, qkvb, gq, gk, vh);

    rope_cvt<<<TOTAL, 640>>>(gq, gk, cosb, sinb, qh, ql, kh);

    attn_mma<<<dim3(CHUNK / 128, HEADS, NCHUNKS), ANTHR, ASMEM>>>(
        qh, ql, kh, vh, aoh);

    mma_gemm<1><<<dim3(DIM / 128, TOTAL / 128), NTHR, GSMEM>>>(
        aoh, wph, projb, out,
        (float*)nullptr, (__half*)nullptr);
}

// round 17
// speedup vs baseline: 2.5648x; 1.0632x over previous
#include <cuda_runtime.h>
#include <cuda_bf16.h>
#include <cuda_fp16.h>
#include <cstdint>
#include <cstddef>

#define TOTAL   8192
#define DIM     1280
#define HEADS   16
#define HD      80
#define NCHUNKS 8
#define CHUNK   1024
#define K_DIM   1280
#define N_QKV   3840

// ---------------- scratch (device globals) ----------------------------------
__device__ float g_q [TOTAL * DIM];
__device__ float g_k [TOTAL * DIM];

__device__ __half g_hs_h[TOTAL * K_DIM];
__device__ __half g_wq_h[N_QKV * K_DIM];
__device__ __half g_wp_h[DIM * K_DIM];
__device__ __half g_ao_h[TOTAL * DIM];

__device__ __half g_qh[TOTAL * DIM];
__device__ __half g_kh[TOTAL * DIM];
__device__ __half g_vh[TOTAL * DIM];

// ---------------- PTX helpers ------------------------------------------------
__device__ __forceinline__ uint32_t smem_u32(const void* p) {
    uint32_t r;
    asm("{ .reg .u64 t; cvta.to.shared.u64 t, %1; cvt.u32.u64 %0, t; }"
        : "=r"(r) : "l"(p));
    return r;
}
__device__ __forceinline__ void cp16(uint32_t dst, const void* src) {
    asm volatile("cp.async.cg.shared.global [%0], [%1], 16;" :: "r"(dst), "l"(src));
}
__device__ __forceinline__ void ldmx4(uint32_t* a, uint32_t addr) {
    asm volatile("ldmatrix.sync.aligned.m8n8.x4.shared.b16 {%0,%1,%2,%3}, [%4];"
                 : "=r"(a[0]), "=r"(a[1]), "=r"(a[2]), "=r"(a[3]) : "r"(addr));
}
__device__ __forceinline__ void ldmx4t(uint32_t* a, uint32_t addr) {
    asm volatile("ldmatrix.sync.aligned.m8n8.x4.trans.shared.b16 {%0,%1,%2,%3}, [%4];"
                 : "=r"(a[0]), "=r"(a[1]), "=r"(a[2]), "=r"(a[3]) : "r"(addr));
}
__device__ __forceinline__ void ldmB(uint32_t* b, uint32_t addr) {
    asm volatile("ldmatrix.sync.aligned.m8n8.x2.shared.b16 {%0,%1}, [%2];"
                 : "=r"(b[0]), "=r"(b[1]) : "r"(addr));
}
// fp16 mma
__device__ __forceinline__ void mma16816h(float* d, const uint32_t* a, const uint32_t* b) {
    asm volatile(
        "mma.sync.aligned.m16n8k16.row.col.f32.f16.f16.f32 "
        "{%0,%1,%2,%3}, {%4,%5,%6,%7}, {%8,%9}, {%0,%1,%2,%3};"
        : "+f"(d[0]), "+f"(d[1]), "+f"(d[2]), "+f"(d[3])
        : "r"(a[0]), "r"(a[1]), "r"(a[2]), "r"(a[3]), "r"(b[0]), "r"(b[1]));
}
__device__ __forceinline__ float ex2(float x) {
    float r;
    asm("ex2.approx.f32 %0, %1;" : "=f"(r) : "f"(x));
    return r;
}
// mbarrier ops
__device__ __forceinline__ void mbar_init(uint32_t addr, uint32_t cnt) {
    asm volatile("mbarrier.init.shared.b64 [%0], %1;" :: "r"(addr), "r"(cnt) : "memory");
}
__device__ __forceinline__ void mbar_arrive(uint32_t addr) {
    asm volatile("mbarrier.arrive.shared.b64 _, [%0];" :: "r"(addr) : "memory");
}
__device__ __forceinline__ void cpasync_mbar_arrive(uint32_t addr) {
    asm volatile("cp.async.mbarrier.arrive.noinc.shared.b64 [%0];" :: "r"(addr) : "memory");
}
__device__ __forceinline__ void mbar_wait(uint32_t addr, uint32_t parity) {
    asm volatile(
        "{\n\t"
        ".reg .pred P1;\n\t"
        "WL%=:\n\t"
        "mbarrier.try_wait.parity.acquire.cta.shared::cta.b64 P1, [%0], %1, 0x989680;\n\t"
        "@P1 bra WD%=;\n\t"
        "bra WL%=;\n\t"
        "WD%=:\n\t"
        "}"
        :: "r"(addr), "r"(parity) : "memory");
}

// ---------------------------------------------------------------------------
// fp32 -> fp16 (single rounding)
// ---------------------------------------------------------------------------
__global__ void cvt_h1(const float* __restrict__ x, __half* __restrict__ h, int n4)
{
    int i = blockIdx.x * blockDim.x + threadIdx.x;
    if (i >= n4) return;
    float4 f = ((const float4*)x)[i];
    __half2 p0 = __floats2half2_rn(f.x, f.y);
    __half2 p1 = __floats2half2_rn(f.z, f.w);
    ((uint32_t*)h)[i * 2 + 0] = *(uint32_t*)&p0;
    ((uint32_t*)h)[i * 2 + 1] = *(uint32_t*)&p1;
}

// ---------------------------------------------------------------------------
// Warp-specialized fp16 GEMM, single-pass: C = A*B + bias  (R16 exact)
// 8 consumer warps (64x32) + 2 producer warps, 5-stage pipeline.
// EPI==0: parts 0/1 (Q,K) -> fp32 O0/O1; part 2 (V) -> fp16 Ovh.
// EPI==1: fp32 store to O0.
// ---------------------------------------------------------------------------
#define KC       32
#define NCH      40
#define STRIDE   40
#define TILE_B   (128 * STRIDE * 2)    // 10240
#define STAGE_B  (2 * TILE_B)          // 20480 (A, B)
#define NSTG     5
#define GSMEM    (NSTG * STAGE_B)      // 102400
#define NCONS    256
#define NPROD    64
#define NTHR     (NCONS + NPROD)

template <int EPI>
__global__ __launch_bounds__(NTHR, 1)
void mma_gemm(const __half* __restrict__ A, const __half* __restrict__ B,
              const float* __restrict__ bias,
              float* __restrict__ O0, float* __restrict__ O1,
              __half* __restrict__ Ovh)
{
    extern __shared__ __half smem[];
    __shared__ __align__(8) uint64_t bar_full [NSTG];
    __shared__ __align__(8) uint64_t bar_empty[NSTG];

    const uint32_t sbase = smem_u32(smem);
    const int tid  = threadIdx.x;
    const int m0   = blockIdx.y * 128;
    const int n0   = blockIdx.x * 128;

    uint32_t full[NSTG], empty[NSTG];
#pragma unroll
    for (int s = 0; s < NSTG; s++) {
        full[s]  = smem_u32(&bar_full[s]);
        empty[s] = smem_u32(&bar_empty[s]);
    }
    if (tid == 0) {
#pragma unroll
        for (int s = 0; s < NSTG; s++) {
            mbar_init(full[s],  NPROD);
            mbar_init(empty[s], NCONS);
        }
    }
    __syncthreads();

    if (tid >= NCONS) {
        // ---------------- producer warps --------------------------------------
        const int ptid = tid - NCONS;    // 0..63
        const __half* srcs[2] = {
            A + (size_t)m0 * K_DIM, B + (size_t)n0 * K_DIM };
        int stage = 0, phase = 1;
        for (int ch = 0; ch < NCH; ch++) {
            mbar_wait(empty[stage], phase);
            const int k0 = ch * KC;
            const uint32_t sb = sbase + stage * STAGE_B;
#pragma unroll
            for (int t = 0; t < 16; t++) {
                int idx  = ptid + t * 64;   // 0..1023
                int tile = idx >> 9;        // 0..1
                int rem  = idx & 511;
                int row  = rem >> 2;
                int seg  = rem & 3;
                cp16(sb + tile * TILE_B + row * (STRIDE * 2) + seg * 16,
                     srcs[tile] + (size_t)row * K_DIM + k0 + seg * 8);
            }
            cpasync_mbar_arrive(full[stage]);
            if (++stage == NSTG) { stage = 0; phase ^= 1; }
        }
        return;
    }

    // ---------------- consumer warps ------------------------------------------
    const int wid  = tid >> 5;
    const int lane = tid & 31;
    const int wm   = (wid >> 2) * 64;
    const int wn   = (wid & 3) * 32;

    float acc[4][4][4];
#pragma unroll
    for (int i = 0; i < 4; i++)
#pragma unroll
        for (int j = 0; j < 4; j++)
#pragma unroll
            for (int r = 0; r < 4; r++) acc[i][j][r] = 0.f;

    const int arow  = lane & 15;
    const int acol8 = (lane >> 4) * 8;
    const int brow  = lane & 7;
    const int bcolo = ((lane >> 3) & 1) * 8;

    int stage = 0, phase = 0;
    for (int ch = 0; ch < NCH; ch++) {
        mbar_wait(full[stage], phase);

        const uint32_t sb = sbase + stage * STAGE_B;
        const uint32_t sA = sb;
        const uint32_t sB = sb + TILE_B;

#pragma unroll
        for (int kk = 0; kk < 2; kk++) {
            uint32_t aH[16];
#pragma unroll
            for (int mt = 0; mt < 4; mt++) {
                uint32_t off = ((wm + mt * 16 + arow) * STRIDE + kk * 16 + acol8) * 2;
                ldmx4(aH + mt * 4, sA + off);
            }
#pragma unroll
            for (int nt = 0; nt < 4; nt++) {
                uint32_t bh[2];
                uint32_t off = ((wn + nt * 8 + brow) * STRIDE + kk * 16 + bcolo) * 2;
                ldmB(bh, sB + off);
#pragma unroll
                for (int mt = 0; mt < 4; mt++)
                    mma16816h(acc[mt][nt], aH + mt * 4, bh);
            }
        }
        mbar_arrive(empty[stage]);
        if (++stage == NSTG) { stage = 0; phase ^= 1; }
    }

    // ---- epilogue ----
    if (EPI == 0 && n0 >= 2 * DIM) {
        const int ccol0 = n0 - 2 * DIM;
#pragma unroll
        for (int mt = 0; mt < 4; mt++) {
#pragma unroll
            for (int nt = 0; nt < 4; nt++) {
                int row   = m0 + wm + mt * 16 + (lane >> 2);
                int bcolg = n0 + wn + nt * 8 + (lane & 3) * 2;
                int col   = ccol0 + wn + nt * 8 + (lane & 3) * 2;
                float2 bb = *(const float2*)&bias[bcolg];
                __half2 v0 = __floats2half2_rn(acc[mt][nt][0] + bb.x,
                                               acc[mt][nt][1] + bb.y);
                __half2 v1 = __floats2half2_rn(acc[mt][nt][2] + bb.x,
                                               acc[mt][nt][3] + bb.y);
                *(uint32_t*)&Ovh[(size_t)row * DIM + col]       = *(uint32_t*)&v0;
                *(uint32_t*)&Ovh[(size_t)(row + 8) * DIM + col] = *(uint32_t*)&v1;
            }
        }
    } else {
        float* dst;
        int ccol0;
        if (EPI == 0) {
            int part = n0 / DIM;
            dst   = (part == 0) ? O0 : O1;
            ccol0 = n0 - part * DIM;
        } else {
            dst   = O0;
            ccol0 = n0;
        }
#pragma unroll
        for (int mt = 0; mt < 4; mt++) {
#pragma unroll
            for (int nt = 0; nt < 4; nt++) {
                int row   = m0 + wm + mt * 16 + (lane >> 2);
                int bcolg = n0 + wn + nt * 8 + (lane & 3) * 2;
                int col   = ccol0 + wn + nt * 8 + (lane & 3) * 2;
                float2 bb = *(const float2*)&bias[bcolg];
                float2 v0, v1;
                v0.x = acc[mt][nt][0] + bb.x;  v0.y = acc[mt][nt][1] + bb.y;
                v1.x = acc[mt][nt][2] + bb.x;  v1.y = acc[mt][nt][3] + bb.y;
                *(float2*)&dst[(size_t)row * DIM + col]       = v0;
                *(float2*)&dst[(size_t)(row + 8) * DIM + col] = v1;
            }
        }
    }
}

// ---------------------------------------------------------------------------
// RoPE + scale: q -> fp16 single (scaled), k -> fp16 single
// ---------------------------------------------------------------------------
__global__ __launch_bounds__(640)
void rope_cvt(const float* __restrict__ gq, const float* __restrict__ gk,
              const float* __restrict__ cosb, const float* __restrict__ sinb,
              __half* __restrict__ qh, __half* __restrict__ kh)
{
    const float QSC = 0.11180339887498949f * 1.4426950408889634f;
    const int t = blockIdx.x;
    const int p = threadIdx.x;

    int h = p / 40, d = p - (p / 40) * 40;
    size_t base = (size_t)t * DIM + h * HD;
    float c0 = cosb[t * HD + d],      s0 = sinb[t * HD + d];
    float c1 = cosb[t * HD + d + 40], s1 = sinb[t * HD + d + 40];

    float a = gq[base + d], b = gq[base + d + 40];
    qh[base + d]      = __float2half_rn((a * c0 - b * s0) * QSC);
    qh[base + d + 40] = __float2half_rn((b * c1 + a * s1) * QSC);

    a = gk[base + d]; b = gk[base + d + 40];
    kh[base + d]      = __float2half_rn(a * c0 - b * s0);
    kh[base + d + 40] = __float2half_rn(b * c1 + a * s1);
}

// ---------------------------------------------------------------------------
// Flash attention on fp16 mma.sync: S = Q K (1-pass), O += P V (1-pass).
// 8 consumer warps + 2 producer warps, 5-stage KV ring. Output single fp16.
// ---------------------------------------------------------------------------
#define AST      88
#define ATB      (64 * AST)
#define ASTAGE   (2 * ATB)
#define ANSTG    5
#define ASMEM    (ANSTG * ASTAGE * 2)  // 112640 B
#define ANCONS   256
#define ANPROD   64
#define ANTHR    (ANCONS + ANPROD)

__global__ __launch_bounds__(ANTHR, 1)
void attn_mma(const __half* __restrict__ qh, const __half* __restrict__ kh,
              const __half* __restrict__ vh, __half* __restrict__ aoh)
{
    extern __shared__ __half asmem[];
    __shared__ __align__(8) uint64_t abar_full [ANSTG];
    __shared__ __align__(8) uint64_t abar_empty[ANSTG];

    const uint32_t sbase = smem_u32(asmem);
    const int tid   = threadIdx.x;
    const int chunk = blockIdx.z;
    const int head  = blockIdx.y;
    const int q0    = blockIdx.x * 128;

    uint32_t full[ANSTG], empty[ANSTG];
#pragma unroll
    for (int s = 0; s < ANSTG; s++) {
        full[s]  = smem_u32(&abar_full[s]);
        empty[s] = smem_u32(&abar_empty[s]);
    }
    if (tid == 0) {
#pragma unroll
        for (int s = 0; s < ANSTG; s++) {
            mbar_init(full[s],  ANPROD);
            mbar_init(empty[s], ANCONS);
        }
    }

    // ---- stage Q through smem ---------------------------------------------------
    if (tid < ANCONS) {
#pragma unroll
        for (int t = 0; t < 5; t++) {
            int idx = tid + t * 256;          // 0..1279
            int row = idx / 10;
            int seg = idx - row * 10;
            cp16(sbase + (row * AST + seg * 8) * 2,
                 qh + (size_t)(chunk * CHUNK + q0 + row) * DIM + head * HD + seg * 8);
        }
        asm volatile("cp.async.commit_group;");
        asm volatile("cp.async.wait_group 0;");
    }
    __syncthreads();

    if (tid >= ANCONS) {
        // ---------------- producer warps ----------------------------------------
        const int ptid = tid - ANCONS;
        __syncthreads();                 // consumers finish reading Q from smem
        const __half* srckv[2] = { kh, vh };
        int st = 0, ph = 1;
        for (int t = 0; t < 16; t++) {
            mbar_wait(empty[st], ph);
            const int krow0 = chunk * CHUNK + t * 64;
            const uint32_t sb = sbase + (st * ASTAGE) * 2;
#pragma unroll
            for (int it = 0; it < 20; it++) {
                int idx = ptid + it * 64;
                int buf = idx / 640;
                int rem = idx - buf * 640;
                int row = rem / 10;
                int seg = rem - row * 10;
                cp16(sb + (buf * ATB + row * AST + seg * 8) * 2,
                     srckv[buf] + (size_t)(krow0 + row) * DIM + head * HD + seg * 8);
            }
            cpasync_mbar_arrive(full[st]);
            if (++st == ANSTG) { st = 0; ph ^= 1; }
        }
        return;
    }

    // ---------------- consumer warps --------------------------------------------
    const int wid  = tid >> 5;
    const int lane = tid & 31;
    const int wm   = wid * 16;

    uint32_t aQh[5][4];
    {
        const int arow = lane & 15;
        const int acol8 = 8 * (lane >> 4);
#pragma unroll
        for (int ks = 0; ks < 5; ks++) {
            uint32_t off = ((wm + arow) * AST + ks * 16 + acol8) * 2;
            ldmx4(aQh[ks], sbase + off);
        }
    }
    __syncthreads();   // release smem to producers

    float o[10][4];
#pragma unroll
    for (int i = 0; i < 10; i++)
#pragma unroll
        for (int r = 0; r < 4; r++) o[i][r] = 0.f;
    float mrow0 = -1e30f, mrow1 = -1e30f, lrow0 = 0.f, lrow1 = 0.f;

    int st = 0, ph = 0;
    for (int t = 0; t < 16; t++) {
        mbar_wait(full[st], ph);

        const uint32_t sb = sbase + (st * ASTAGE) * 2;
        const uint32_t sK = sb;
        const uint32_t sV = sb + ATB * 2;

        // ---- S = Q K^T (1 pass) ----------------------------------------------------
        float S[8][4];
#pragma unroll
        for (int f = 0; f < 8; f++)
#pragma unroll
            for (int r = 0; r < 4; r++) S[f][r] = 0.f;

#pragma unroll
        for (int ks = 0; ks < 5; ks++) {
#pragma unroll
            for (int ng = 0; ng < 4; ng++) {
                uint32_t bh[4];
                uint32_t off = ((ng * 16 + 8 * (lane >> 4) + (lane & 7)) * AST
                                + ks * 16 + 8 * ((lane >> 3) & 1)) * 2;
                ldmx4(bh, sK + off);
                mma16816h(S[2 * ng],     aQh[ks], bh);
                mma16816h(S[2 * ng + 1], aQh[ks], bh + 2);
            }
        }

        // ---- online softmax (base 2) --------------------------------------------
        float mx0 = S[0][0], mx1 = S[0][2];
#pragma unroll
        for (int f = 0; f < 8; f++) {
            mx0 = fmaxf(mx0, fmaxf(S[f][0], S[f][1]));
            mx1 = fmaxf(mx1, fmaxf(S[f][2], S[f][3]));
        }
        mx0 = fmaxf(mx0, __shfl_xor_sync(0xffffffff, mx0, 1));
        mx0 = fmaxf(mx0, __shfl_xor_sync(0xffffffff, mx0, 2));
        mx1 = fmaxf(mx1, __shfl_xor_sync(0xffffffff, mx1, 1));
        mx1 = fmaxf(mx1, __shfl_xor_sync(0xffffffff, mx1, 2));

        float mn0 = fmaxf(mrow0, mx0), mn1 = fmaxf(mrow1, mx1);
        float al0 = ex2(mrow0 - mn0),  al1 = ex2(mrow1 - mn1);
        mrow0 = mn0; mrow1 = mn1;
#pragma unroll
        for (int i = 0; i < 10; i++) {
            o[i][0] *= al0; o[i][1] *= al0;
            o[i][2] *= al1; o[i][3] *= al1;
        }
        float rs0 = 0.f, rs1 = 0.f;
#pragma unroll
        for (int f = 0; f < 8; f++) {
            S[f][0] = ex2(S[f][0] - mn0); rs0 += S[f][0];
            S[f][1] = ex2(S[f][1] - mn0); rs0 += S[f][1];
            S[f][2] = ex2(S[f][2] - mn1); rs1 += S[f][2];
            S[f][3] = ex2(S[f][3] - mn1); rs1 += S[f][3];
        }
        rs0 += __shfl_xor_sync(0xffffffff, rs0, 1);
        rs0 += __shfl_xor_sync(0xffffffff, rs0, 2);
        rs1 += __shfl_xor_sync(0xffffffff, rs1, 1);
        rs1 += __shfl_xor_sync(0xffffffff, rs1, 2);
        lrow0 = lrow0 * al0 + rs0;
        lrow1 = lrow1 * al1 + rs1;

        // ---- P (single fp16 a-frags) ----------------------------------------------
        uint32_t pH[4][4];
#pragma unroll
        for (int j = 0; j < 4; j++) {
            __half2 p0 = __floats2half2_rn(S[2 * j][0],     S[2 * j][1]);
            __half2 p1 = __floats2half2_rn(S[2 * j][2],     S[2 * j][3]);
            __half2 p2 = __floats2half2_rn(S[2 * j + 1][0], S[2 * j + 1][1]);
            __half2 p3 = __floats2half2_rn(S[2 * j + 1][2], S[2 * j + 1][3]);
            pH[j][0] = *(uint32_t*)&p0;
            pH[j][1] = *(uint32_t*)&p1;
            pH[j][2] = *(uint32_t*)&p2;
            pH[j][3] = *(uint32_t*)&p3;
        }

        // ---- O += P V (1 pass) -------------------------------------------------------
#pragma unroll
        for (int j = 0; j < 4; j++) {
#pragma unroll
            for (int ng = 0; ng < 5; ng++) {
                uint32_t bv[4];
                uint32_t off = ((j * 16 + (lane & 15)) * AST
                                + ng * 16 + 8 * (lane >> 4)) * 2;
                ldmx4t(bv, sV + off);
                mma16816h(o[2 * ng],     pH[j], bv);
                mma16816h(o[2 * ng + 1], pH[j], bv + 2);
            }
        }
        mbar_arrive(empty[st]);
        if (++st == ANSTG) { st = 0; ph ^= 1; }
    }

    // ---- normalize + store single fp16 ------------------------------------------
    float inv0 = 1.f / lrow0, inv1 = 1.f / lrow1;
    const int row0 = chunk * CHUNK + q0 + wm + (lane >> 2);
    const int col0 = head * HD + 2 * (lane & 3);
#pragma unroll
    for (int nt = 0; nt < 10; nt++) {
        size_t idx0 = (size_t)row0 * DIM + col0 + nt * 8;
        __half2 v0 = __floats2half2_rn(o[nt][0] * inv0, o[nt][1] * inv0);
        *(uint32_t*)&aoh[idx0] = *(uint32_t*)&v0;
        size_t idx1 = (size_t)(row0 + 8) * DIM + col0 + nt * 8;
        __half2 v1 = __floats2half2_rn(o[nt][2] * inv1, o[nt][3] * inv1);
        *(uint32_t*)&aoh[idx1] = *(uint32_t*)&v1;
    }
}

// ---------------------------------------------------------------------------
// Launch
// ---------------------------------------------------------------------------
extern "C" void kernel_launch(void* const* d_in, const int* in_sizes, int n_in,
                              void* d_out, int out_size)
{
    const float* hs    = (const float*)d_in[0];
    const float* cosb  = (const float*)d_in[1];
    const float* sinb  = (const float*)d_in[2];
    const float* qkvw  = (const float*)d_in[3];
    const float* qkvb  = (const float*)d_in[4];
    const float* projw = (const float*)d_in[5];
    const float* projb = (const float*)d_in[6];
    float* out = (float*)d_out;
    (void)in_sizes; (void)n_in; (void)out_size;

    float *gq, *gk;
    cudaGetSymbolAddress((void**)&gq, g_q);
    cudaGetSymbolAddress((void**)&gk, g_k);

    __half *hsh, *wqh, *wph, *aoh, *qh, *kh, *vh;
    cudaGetSymbolAddress((void**)&hsh, g_hs_h);
    cudaGetSymbolAddress((void**)&wqh, g_wq_h);
    cudaGetSymbolAddress((void**)&wph, g_wp_h);
    cudaGetSymbolAddress((void**)&aoh, g_ao_h);
    cudaGetSymbolAddress((void**)&qh, g_qh);
    cudaGetSymbolAddress((void**)&kh, g_kh);
    cudaGetSymbolAddress((void**)&vh, g_vh);

    cudaFuncSetAttribute(mma_gemm<0>, cudaFuncAttributeMaxDynamicSharedMemorySize, GSMEM);
    cudaFuncSetAttribute(mma_gemm<1>, cudaFuncAttributeMaxDynamicSharedMemorySize, GSMEM);
    cudaFuncSetAttribute(attn_mma,    cudaFuncAttributeMaxDynamicSharedMemorySize, ASMEM);

    cvt_h1<<<(TOTAL * K_DIM / 4 + 255) / 256, 256>>>(hs, hsh, TOTAL * K_DIM / 4);
    cvt_h1<<<(N_QKV * K_DIM / 4 + 255) / 256, 256>>>(qkvw, wqh, N_QKV * K_DIM / 4);
    cvt_h1<<<(DIM * K_DIM / 4 + 255) / 256, 256>>>(projw, wph, DIM * K_DIM / 4);

    // QKV projection: Q,K -> fp32 (for RoPE), V -> fp16 directly
    mma_gemm<0><<<dim3(N_QKV / 128, TOTAL / 128), NTHR, GSMEM>>>(
        hsh, wqh, qkvb, gq, gk, vh);

    rope_cvt<<<TOTAL, 640>>>(gq, gk, cosb, sinb, qh, kh);

    attn_mma<<<dim3(CHUNK / 128, HEADS, NCHUNKS), ANTHR, ASMEM>>>(
        qh, kh, vh, aoh);

    mma_gemm<1><<<dim3(DIM / 128, TOTAL / 128), NTHR, GSMEM>>>(
        aoh, wph, projb, out,
        (float*)nullptr, (__half*)nullptr);
}